// round 7
// baseline (speedup 1.0000x reference)
#include <cuda_runtime.h>
#include <math.h>

// Problem constants
#define BATCH 2
#define SEQ 2048
#define DMODEL 1024
#define NHEADS 16
#define HDIM 64
#define MTOT (BATCH * SEQ)                 // 4096
#define OUT_ELEMS ((size_t)MTOT * DMODEL)  // 4,194,304
#define APH ((size_t)SEQ * SEQ)            // per-head attn elems

// Scratch (allocation-free rule: __device__ globals)
__device__ float g_q[MTOT * DMODEL];
__device__ float g_k[MTOT * DMODEL];
__device__ float g_v[MTOT * DMODEL];
__device__ float g_ctx[MTOT * DMODEL];
// Row-sum partials: [z(32)][ntile(16)][row(2048)]
__device__ float g_rsum[32 * 16 * 2048];

// ---------- tf32 helpers ----------
__device__ __forceinline__ unsigned f2t(float x) {
    unsigned u;
    asm("cvt.rna.tf32.f32 %0, %1;" : "=r"(u) : "f"(x));
    return u;
}

__device__ __forceinline__ void mma8(float* d, const unsigned* a, const unsigned* b) {
    asm volatile(
        "mma.sync.aligned.m16n8k8.row.col.f32.tf32.tf32.f32 "
        "{%0,%1,%2,%3}, {%4,%5,%6,%7}, {%8,%9}, {%0,%1,%2,%3};\n"
        : "+f"(d[0]), "+f"(d[1]), "+f"(d[2]), "+f"(d[3])
        : "r"(a[0]), "r"(a[1]), "r"(a[2]), "r"(a[3]), "r"(b[0]), "r"(b[1]));
}

#define PBK 16  // K-chunk per smem stage

// Fragment-ordered smem addressing.
// A tile (M up to 128, K=16): block = (k>>3)*8 + (m>>4), 128 entries/block:
//   off = (m&7)*16 + (k&3)*4 + ((m&8)>>3) + ((k&4)>>1)
// Lane (grp=lane>>2, tig=lane&3) ld.shared.v4 at block*128 + lane*4 yields
// regs (tig,m),(tig,m+8),(tig+4,m),(tig+4,m+8) — exact mma A-fragment order.
// B tile (N, K=16), NT8 = N/8 blocks per k-slice: block = (k>>3)*NT8 + (n>>3),
// 64 entries: off = (n&7)*8 + (k&3)*2 + ((k&4)>>2); v2 at block*64 + lane*2.

// ======================================================================
// GEMM: C[M,N] = A[M,K] @ B[K,N] + bias[N]    (tile 128x128x16, 8 warps)
// ======================================================================
__global__ __launch_bounds__(256, 2) void gemm_bias_tc(
    const float* __restrict__ A, const float* __restrict__ B,
    const float* __restrict__ bias, float* __restrict__ C,
    int M, int N, int K)
{
    __shared__ __align__(16) unsigned sA[2][2048];
    __shared__ __align__(16) unsigned sB[2][2048];

    int tid = threadIdx.x, lane = tid & 31, wid = tid >> 5;
    int grp = lane >> 2, tig = lane & 3;
    int m0 = blockIdx.y * 128, n0 = blockIdx.x * 128;
    int wm = (wid >> 2) * 64, wn = (wid & 3) * 32;
    int wmB = (wid >> 2) * 4, wnB = (wid & 3) * 4;   // fragment block bases

    int ar = tid >> 2, ac = (tid & 3) * 4;   // A tile: 128 rows x 16 cols
    int br = tid >> 5, bc = (tid & 31) * 4;  // B tile: 16 rows x 128 cols

    // STS bases
    int aBase[2], bBase[2];
#pragma unroll
    for (int p = 0; p < 2; p++) {
        aBase[p] = ((ac >> 3) * 8 + (ar >> 4) + p * 4) * 128 +
                   (ar & 7) * 16 + ((ar & 8) >> 3) + ((ac & 4) >> 1);
        int kk = br + p * 8;
        bBase[p] = ((kk >> 3) * 16 + (bc >> 3)) * 64 +
                   (bc & 7) * 8 + (kk & 3) * 2 + ((kk & 4) >> 2);
    }

    float acc[4][4][4] = {};
    float4 ra[2], rb[2];

    auto ldg = [&](int k0) {
        ra[0] = *(const float4*)&A[(size_t)(m0 + ar) * K + k0 + ac];
        ra[1] = *(const float4*)&A[(size_t)(m0 + ar + 64) * K + k0 + ac];
        rb[0] = *(const float4*)&B[(size_t)(k0 + br) * N + n0 + bc];
        rb[1] = *(const float4*)&B[(size_t)(k0 + br + 8) * N + n0 + bc];
    };
    auto sts = [&](int bf) {
        unsigned* pa = sA[bf];
        unsigned* pb = sB[bf];
#pragma unroll
        for (int p = 0; p < 2; p++) {
            const float* f = (const float*)&ra[p];
            const float* g = (const float*)&rb[p];
#pragma unroll
            for (int j = 0; j < 4; j++) {
                pa[aBase[p] + j * 4] = f2t(f[j]);
                pb[bBase[p] + j * 8] = f2t(g[j]);
            }
        }
    };

    int NIT = K / PBK;
    ldg(0);
    sts(0);
    __syncthreads();

    for (int it = 0; it < NIT; ++it) {
        int cur = it & 1;
        if (it + 1 < NIT) ldg((it + 1) * PBK);
        const unsigned* sa = sA[cur];
        const unsigned* sb = sB[cur];
#pragma unroll
        for (int ks = 0; ks < 2; ks++) {
            uint4 afv[4];
            uint2 bfv[4];
#pragma unroll
            for (int mi = 0; mi < 4; mi++)
                afv[mi] = *(const uint4*)&sa[((ks * 8 + wmB + mi) << 7) + (lane << 2)];
#pragma unroll
            for (int ni = 0; ni < 4; ni++)
                bfv[ni] = *(const uint2*)&sb[((ks * 16 + wnB + ni) << 6) + (lane << 1)];
#pragma unroll
            for (int mi = 0; mi < 4; mi++)
#pragma unroll
                for (int ni = 0; ni < 4; ni++)
                    mma8(acc[mi][ni], (const unsigned*)&afv[mi], (const unsigned*)&bfv[ni]);
        }
        if (it + 1 < NIT) sts(cur ^ 1);
        __syncthreads();
    }

#pragma unroll
    for (int mi = 0; mi < 4; mi++) {
        int row = m0 + wm + mi * 16 + grp;
#pragma unroll
        for (int ni = 0; ni < 4; ni++) {
            int col = n0 + wn + ni * 8 + 2 * tig;
            float b0 = bias[col], b1 = bias[col + 1];
            C[(size_t)row * N + col]           = acc[mi][ni][0] + b0;
            C[(size_t)row * N + col + 1]       = acc[mi][ni][1] + b1;
            C[(size_t)(row + 8) * N + col]     = acc[mi][ni][2] + b0;
            C[(size_t)(row + 8) * N + col + 1] = acc[mi][ni][3] + b1;
        }
    }
}

// ======================================================================
// Scores+exp: attn[z,q,k] = exp((Q_z @ K_z^T) * 0.125), row-sum partials
// ======================================================================
__global__ __launch_bounds__(256, 2) void scores_exp_tc(
    const float* __restrict__ Q, const float* __restrict__ Km,
    float* __restrict__ attn)
{
    __shared__ __align__(16) unsigned sA[2][2048];
    __shared__ __align__(16) unsigned sB[2][2048];
    __shared__ float srs[128];

    int tid = threadIdx.x, lane = tid & 31, wid = tid >> 5;
    int grp = lane >> 2, tig = lane & 3;
    int q0 = blockIdx.y * 128, n0 = blockIdx.x * 128;
    int z = blockIdx.z, b = z / NHEADS, h = z % NHEADS;
    int wm = (wid >> 2) * 64, wn = (wid & 3) * 32;
    int wmB = (wid >> 2) * 4, wnB = (wid & 3) * 4;
    int ar = tid >> 2, ac = (tid & 3) * 4;

    if (tid < 128) srs[tid] = 0.f;

    const float* Qb = Q + (size_t)b * SEQ * DMODEL + h * HDIM;
    const float* Kb = Km + (size_t)b * SEQ * DMODEL + h * HDIM;

    int aBase[2], bBase[2];
#pragma unroll
    for (int p = 0; p < 2; p++) {
        aBase[p] = ((ac >> 3) * 8 + (ar >> 4) + p * 4) * 128 +
                   (ar & 7) * 16 + ((ar & 8) >> 3) + ((ac & 4) >> 1);
        bBase[p] = ((ac >> 3) * 16 + (ar >> 3) + p * 8) * 64 +
                   (ar & 7) * 8 + ((ac & 4) >> 2);
    }

    float acc[4][4][4] = {};
    float4 ra[2], rk[2];

    auto ldg = [&](int k0) {
        ra[0] = *(const float4*)&Qb[(size_t)(q0 + ar) * DMODEL + k0 + ac];
        ra[1] = *(const float4*)&Qb[(size_t)(q0 + ar + 64) * DMODEL + k0 + ac];
        rk[0] = *(const float4*)&Kb[(size_t)(n0 + ar) * DMODEL + k0 + ac];
        rk[1] = *(const float4*)&Kb[(size_t)(n0 + ar + 64) * DMODEL + k0 + ac];
    };
    auto sts = [&](int bf) {
        unsigned* pa = sA[bf];
        unsigned* pb = sB[bf];
#pragma unroll
        for (int p = 0; p < 2; p++) {
            const float* f = (const float*)&ra[p];
            const float* g = (const float*)&rk[p];
#pragma unroll
            for (int j = 0; j < 4; j++) {
                pa[aBase[p] + j * 4] = f2t(f[j]);
                pb[bBase[p] + j * 2] = f2t(g[j]);
            }
        }
    };

    const int NIT = HDIM / PBK;  // 4
    ldg(0);
    sts(0);
    __syncthreads();

    for (int it = 0; it < NIT; ++it) {
        int cur = it & 1;
        if (it + 1 < NIT) ldg((it + 1) * PBK);
        const unsigned* sa = sA[cur];
        const unsigned* sb = sB[cur];
#pragma unroll
        for (int ks = 0; ks < 2; ks++) {
            uint4 afv[4];
            uint2 bfv[4];
#pragma unroll
            for (int mi = 0; mi < 4; mi++)
                afv[mi] = *(const uint4*)&sa[((ks * 8 + wmB + mi) << 7) + (lane << 2)];
#pragma unroll
            for (int ni = 0; ni < 4; ni++)
                bfv[ni] = *(const uint2*)&sb[((ks * 16 + wnB + ni) << 6) + (lane << 1)];
#pragma unroll
            for (int mi = 0; mi < 4; mi++)
#pragma unroll
                for (int ni = 0; ni < 4; ni++)
                    mma8(acc[mi][ni], (const unsigned*)&afv[mi], (const unsigned*)&bfv[ni]);
        }
        if (it + 1 < NIT) sts(cur ^ 1);
        __syncthreads();
    }

    // Epilogue: exp(scale * s), write, per-row partial sums
    float* S = attn + (size_t)z * APH;
    const float scale = 0.125f;  // 1/sqrt(64)
    float rsum[4][2] = {};
#pragma unroll
    for (int mi = 0; mi < 4; mi++) {
        int row = q0 + wm + mi * 16 + grp;
#pragma unroll
        for (int ni = 0; ni < 4; ni++) {
            int col = n0 + wn + ni * 8 + 2 * tig;
            float e0 = __expf(acc[mi][ni][0] * scale);
            float e1 = __expf(acc[mi][ni][1] * scale);
            float e2 = __expf(acc[mi][ni][2] * scale);
            float e3 = __expf(acc[mi][ni][3] * scale);
            S[(size_t)row * SEQ + col]           = e0;
            S[(size_t)row * SEQ + col + 1]       = e1;
            S[(size_t)(row + 8) * SEQ + col]     = e2;
            S[(size_t)(row + 8) * SEQ + col + 1] = e3;
            rsum[mi][0] += e0 + e1;
            rsum[mi][1] += e2 + e3;
        }
    }
#pragma unroll
    for (int mi = 0; mi < 4; mi++)
#pragma unroll
        for (int r = 0; r < 2; r++) {
            float v = rsum[mi][r];
            v += __shfl_xor_sync(~0u, v, 1);
            v += __shfl_xor_sync(~0u, v, 2);
            if (tig == 0) atomicAdd(&srs[wm + mi * 16 + grp + r * 8], v);
        }
    __syncthreads();
    if (tid < 128)
        g_rsum[((size_t)z * 16 + blockIdx.x) * 2048 + q0 + tid] = srs[tid];
}

// ======================================================================
// AV+normalize: ctx = softmax @ V; also writes normalized attn back.
// tile 128x64, K=2048. Each attn element is read by exactly one CTA.
// ======================================================================
__global__ __launch_bounds__(256, 2) void av_norm_tc(
    float* __restrict__ attn, const float* __restrict__ V,
    float* __restrict__ ctx)
{
    __shared__ __align__(16) unsigned sA[2][2048];
    __shared__ __align__(16) unsigned sB[2][1024];
    __shared__ float sinv[128];

    int tid = threadIdx.x, lane = tid & 31, wid = tid >> 5;
    int grp = lane >> 2, tig = lane & 3;
    int m0 = blockIdx.x * 128;
    int z = blockIdx.y, b = z / NHEADS, h = z % NHEADS;
    int wm = (wid >> 1) * 32, wn = (wid & 1) * 32;
    int wmB = (wid >> 1) * 2, wnB = (wid & 1) * 4;
    int ar = tid >> 2, ac = (tid & 3) * 4;   // A tile 128x16
    int rv = tid >> 4, cv = (tid & 15) * 4;  // V tile 16x64

    float* Ab = attn + (size_t)z * APH;
    const float* Vb = V + (size_t)b * SEQ * DMODEL + h * HDIM;

    // Row inverse sums from partials
    if (tid < 128) {
        float s = 0.f;
#pragma unroll
        for (int t = 0; t < 16; t++)
            s += g_rsum[((size_t)z * 16 + t) * 2048 + m0 + tid];
        sinv[tid] = 1.f / s;
    }
    __syncthreads();

    int aBase[2], vBase;
#pragma unroll
    for (int p = 0; p < 2; p++)
        aBase[p] = ((ac >> 3) * 8 + (ar >> 4) + p * 4) * 128 +
                   (ar & 7) * 16 + ((ar & 8) >> 3) + ((ac & 4) >> 1);
    vBase = ((rv >> 3) * 8 + (cv >> 3)) * 64 +
            (cv & 7) * 8 + (rv & 3) * 2 + ((rv & 4) >> 2);

    float acc[2][4][4] = {};
    float4 ra[2], rb;
    float inv0 = sinv[ar], inv1 = sinv[ar + 64];

    auto ldg = [&](int k0) {
#pragma unroll
        for (int p = 0; p < 2; p++) {
            size_t off = (size_t)(m0 + ar + p * 64) * SEQ + k0 + ac;
            float4 t = *(const float4*)&Ab[off];
            float iv = p ? inv1 : inv0;
            t.x *= iv; t.y *= iv; t.z *= iv; t.w *= iv;
            *(float4*)&Ab[off] = t;   // normalized attn back to gmem
            ra[p] = t;
        }
        rb = *(const float4*)&Vb[(size_t)(k0 + rv) * DMODEL + cv];
    };
    auto sts = [&](int bf) {
        unsigned* pa = sA[bf];
        unsigned* pb = sB[bf];
#pragma unroll
        for (int p = 0; p < 2; p++) {
            const float* f = (const float*)&ra[p];
#pragma unroll
            for (int j = 0; j < 4; j++)
                pa[aBase[p] + j * 4] = f2t(f[j]);
        }
        const float* g = (const float*)&rb;
#pragma unroll
        for (int j = 0; j < 4; j++) pb[vBase + j * 8] = f2t(g[j]);
    };

    const int NIT = SEQ / PBK;  // 128
    ldg(0);
    sts(0);
    __syncthreads();

    for (int it = 0; it < NIT; ++it) {
        int cur = it & 1;
        if (it + 1 < NIT) ldg((it + 1) * PBK);
        const unsigned* sa = sA[cur];
        const unsigned* sb = sB[cur];
#pragma unroll
        for (int ks = 0; ks < 2; ks++) {
            uint4 afv[2];
            uint2 bfv[4];
#pragma unroll
            for (int mi = 0; mi < 2; mi++)
                afv[mi] = *(const uint4*)&sa[((ks * 8 + wmB + mi) << 7) + (lane << 2)];
#pragma unroll
            for (int ni = 0; ni < 4; ni++)
                bfv[ni] = *(const uint2*)&sb[((ks * 8 + wnB + ni) << 6) + (lane << 1)];
#pragma unroll
            for (int mi = 0; mi < 2; mi++)
#pragma unroll
                for (int ni = 0; ni < 4; ni++)
                    mma8(acc[mi][ni], (const unsigned*)&afv[mi], (const unsigned*)&bfv[ni]);
        }
        if (it + 1 < NIT) sts(cur ^ 1);
        __syncthreads();
    }

    float* Cb = ctx + (size_t)b * SEQ * DMODEL + h * HDIM;
#pragma unroll
    for (int mi = 0; mi < 2; mi++) {
        int row = m0 + wm + mi * 16 + grp;
#pragma unroll
        for (int ni = 0; ni < 4; ni++) {
            int col = wn + ni * 8 + 2 * tig;
            Cb[(size_t)row * DMODEL + col]           = acc[mi][ni][0];
            Cb[(size_t)row * DMODEL + col + 1]       = acc[mi][ni][1];
            Cb[(size_t)(row + 8) * DMODEL + col]     = acc[mi][ni][2];
            Cb[(size_t)(row + 8) * DMODEL + col + 1] = acc[mi][ni][3];
        }
    }
}

extern "C" void kernel_launch(void* const* d_in, const int* in_sizes, int n_in,
                              void* d_out, int out_size) {
    const float* x   = (const float*)d_in[0];
    const float* w_q = (const float*)d_in[1];
    const float* b_q = (const float*)d_in[2];
    const float* w_k = (const float*)d_in[3];
    const float* b_k = (const float*)d_in[4];
    const float* w_v = (const float*)d_in[5];
    const float* b_v = (const float*)d_in[6];
    const float* w_o = (const float*)d_in[7];
    const float* b_o = (const float*)d_in[8];

    float* out  = (float*)d_out;
    float* attn = out + OUT_ELEMS;

    float *q, *k, *v, *ctx;
    cudaGetSymbolAddress((void**)&q,   g_q);
    cudaGetSymbolAddress((void**)&k,   g_k);
    cudaGetSymbolAddress((void**)&v,   g_v);
    cudaGetSymbolAddress((void**)&ctx, g_ctx);

    // QKV projections: [4096,1024] @ [1024,1024]
    dim3 g1(DMODEL / 128, MTOT / 128);
    gemm_bias_tc<<<g1, 256>>>(x, w_q, b_q, q, MTOT, DMODEL, DMODEL);
    gemm_bias_tc<<<g1, 256>>>(x, w_k, b_k, k, MTOT, DMODEL, DMODEL);
    gemm_bias_tc<<<g1, 256>>>(x, w_v, b_v, v, MTOT, DMODEL, DMODEL);

    // Scores + exp + row-sum partials
    dim3 g2(SEQ / 128, SEQ / 128, BATCH * NHEADS);
    scores_exp_tc<<<g2, 256>>>(q, k, attn);

    // ctx = softmax @ V, normalized attn written back
    dim3 g3(SEQ / 128, BATCH * NHEADS);
    av_norm_tc<<<g3, 256>>>(attn, v, ctx);

    // out = ctx @ w_o + b_o
    gemm_bias_tc<<<g1, 256>>>(ctx, w_o, b_o, out, MTOT, DMODEL, DMODEL);
}

// round 8
// speedup vs baseline: 1.6477x; 1.6477x over previous
#include <cuda_runtime.h>
#include <math.h>

// Problem constants
#define BATCH 2
#define SEQ 2048
#define DMODEL 1024
#define NHEADS 16
#define HDIM 64
#define MTOT (BATCH * SEQ)                 // 4096
#define OUT_ELEMS ((size_t)MTOT * DMODEL)  // 4,194,304
#define APH ((size_t)SEQ * SEQ)            // per-head attn elems

// Scratch (allocation-free rule: __device__ globals)
__device__ float g_q[MTOT * DMODEL];
__device__ float g_k[MTOT * DMODEL];
__device__ float g_v[MTOT * DMODEL];
__device__ float g_ctx[MTOT * DMODEL];

// ---------- tf32 helpers ----------
__device__ __forceinline__ unsigned f2t(float x) {
    unsigned u;
    asm("cvt.rna.tf32.f32 %0, %1;" : "=r"(u) : "f"(x));
    return u;
}

__device__ __forceinline__ void mma8(float* d, const unsigned* a, const unsigned* b) {
    asm volatile(
        "mma.sync.aligned.m16n8k8.row.col.f32.tf32.tf32.f32 "
        "{%0,%1,%2,%3}, {%4,%5,%6,%7}, {%8,%9}, {%0,%1,%2,%3};\n"
        : "+f"(d[0]), "+f"(d[1]), "+f"(d[2]), "+f"(d[3])
        : "r"(a[0]), "r"(a[1]), "r"(a[2]), "r"(a[3]), "r"(b[0]), "r"(b[1]));
}

#define LDA 132    // 128 + 4 pad (k-major smem row stride, in words)
#define LDBV 68    // 64 + 4 pad for AV's V tile
#define PBK 16     // K-chunk per smem stage

struct GemmArgs {
    const float* A;
    const float* W[3];
    const float* bias[3];
    float* C[3];
};

// ======================================================================
// GEMM: C[z][M,N] = A[M,K] @ W[z][K,N] + bias[z][N]
// CTA tile 128x128x16, 4 warps, warp tile 64x64 (2x2 warp grid)
// ======================================================================
__global__ __launch_bounds__(128) void gemm3_tc(GemmArgs ga, int M, int N, int K)
{
    __shared__ unsigned sA[2][PBK * LDA];
    __shared__ unsigned sB[2][PBK * LDA];

    int tid = threadIdx.x, lane = tid & 31, wid = tid >> 5;
    int grp = lane >> 2, tig = lane & 3;
    int m0 = blockIdx.y * 128, n0 = blockIdx.x * 128;
    int z = blockIdx.z;
    const float* A = ga.A;
    const float* B = ga.W[z];
    const float* bias = ga.bias[z];
    float* C = ga.C[z];

    int wm = (wid >> 1) * 64, wn = (wid & 1) * 64;
    int ar = tid >> 2, ac = (tid & 3) * 4;   // A tile rows 0..31 (+p*32), k cols
    int br = tid >> 5, bc = (tid & 31) * 4;  // B tile k-rows 0..3 (+p*4), n cols

    float acc[4][8][4] = {};
    float4 ra[4], rb[4];

    auto ldg = [&](int k0) {
#pragma unroll
        for (int p = 0; p < 4; p++) {
            ra[p] = *(const float4*)&A[(size_t)(m0 + ar + p * 32) * K + k0 + ac];
            rb[p] = *(const float4*)&B[(size_t)(k0 + br + p * 4) * N + n0 + bc];
        }
    };
    auto sts = [&](int bf) {
        unsigned* pa = sA[bf];
        unsigned* pb = sB[bf];
#pragma unroll
        for (int p = 0; p < 4; p++) {
            const float* f = (const float*)&ra[p];
            const float* g = (const float*)&rb[p];
#pragma unroll
            for (int j = 0; j < 4; j++) {
                pa[(ac + j) * LDA + ar + p * 32] = f2t(f[j]);   // k-major (transposed)
                pb[(br + p * 4) * LDA + bc + j] = f2t(g[j]);    // k-major (direct)
            }
        }
    };

    int NIT = K / PBK;
    ldg(0);
    sts(0);
    __syncthreads();

    for (int it = 0; it < NIT; ++it) {
        int cur = it & 1;
        if (it + 1 < NIT) ldg((it + 1) * PBK);
        const unsigned* sa = sA[cur];
        const unsigned* sb = sB[cur];
#pragma unroll
        for (int ks = 0; ks < 2; ks++) {
            unsigned af[4][4], bf8[8][2];
#pragma unroll
            for (int mi = 0; mi < 4; mi++) {
                int mb = wm + mi * 16 + grp;
                af[mi][0] = sa[(ks * 8 + tig) * LDA + mb];
                af[mi][1] = sa[(ks * 8 + tig) * LDA + mb + 8];
                af[mi][2] = sa[(ks * 8 + tig + 4) * LDA + mb];
                af[mi][3] = sa[(ks * 8 + tig + 4) * LDA + mb + 8];
            }
#pragma unroll
            for (int ni = 0; ni < 8; ni++) {
                int nb = wn + ni * 8 + grp;
                bf8[ni][0] = sb[(ks * 8 + tig) * LDA + nb];
                bf8[ni][1] = sb[(ks * 8 + tig + 4) * LDA + nb];
            }
#pragma unroll
            for (int mi = 0; mi < 4; mi++)
#pragma unroll
                for (int ni = 0; ni < 8; ni++) mma8(acc[mi][ni], af[mi], bf8[ni]);
        }
        if (it + 1 < NIT) sts(cur ^ 1);
        __syncthreads();
    }

#pragma unroll
    for (int mi = 0; mi < 4; mi++) {
        int row = m0 + wm + mi * 16 + grp;
#pragma unroll
        for (int ni = 0; ni < 8; ni++) {
            int col = n0 + wn + ni * 8 + 2 * tig;
            float b0 = bias[col], b1 = bias[col + 1];
            C[(size_t)row * N + col]           = acc[mi][ni][0] + b0;
            C[(size_t)row * N + col + 1]       = acc[mi][ni][1] + b1;
            C[(size_t)(row + 8) * N + col]     = acc[mi][ni][2] + b0;
            C[(size_t)(row + 8) * N + col + 1] = acc[mi][ni][3] + b1;
        }
    }
}

// ======================================================================
// Scores: attn[z,q,k] = (Q_z @ K_z^T) * 0.125
// CTA tile 128x128, K=64; 4 warps, warp tile 64x64
// ======================================================================
__global__ __launch_bounds__(128) void scores_tc(
    const float* __restrict__ Q, const float* __restrict__ Km,
    float* __restrict__ attn)
{
    __shared__ unsigned sA[2][PBK * LDA];
    __shared__ unsigned sB[2][PBK * LDA];

    int tid = threadIdx.x, lane = tid & 31, wid = tid >> 5;
    int grp = lane >> 2, tig = lane & 3;
    int q0 = blockIdx.y * 128, n0 = blockIdx.x * 128;
    int z = blockIdx.z, b = z / NHEADS, h = z % NHEADS;
    int wm = (wid >> 1) * 64, wn = (wid & 1) * 64;
    int ar = tid >> 2, ac = (tid & 3) * 4;

    const float* Qb = Q + (size_t)b * SEQ * DMODEL + h * HDIM;
    const float* Kb = Km + (size_t)b * SEQ * DMODEL + h * HDIM;

    float acc[4][8][4] = {};
    float4 ra[4], rk[4];

    auto ldg = [&](int k0) {
#pragma unroll
        for (int p = 0; p < 4; p++) {
            ra[p] = *(const float4*)&Qb[(size_t)(q0 + ar + p * 32) * DMODEL + k0 + ac];
            rk[p] = *(const float4*)&Kb[(size_t)(n0 + ar + p * 32) * DMODEL + k0 + ac];
        }
    };
    auto sts = [&](int bf) {
        unsigned* pa = sA[bf];
        unsigned* pb = sB[bf];
#pragma unroll
        for (int p = 0; p < 4; p++) {
            const float* f = (const float*)&ra[p];
            const float* g = (const float*)&rk[p];
#pragma unroll
            for (int j = 0; j < 4; j++) {
                pa[(ac + j) * LDA + ar + p * 32] = f2t(f[j]);
                pb[(ac + j) * LDA + ar + p * 32] = f2t(g[j]);
            }
        }
    };

    const int NIT = HDIM / PBK;  // 4
    ldg(0);
    sts(0);
    __syncthreads();

    for (int it = 0; it < NIT; ++it) {
        int cur = it & 1;
        if (it + 1 < NIT) ldg((it + 1) * PBK);
        const unsigned* sa = sA[cur];
        const unsigned* sb = sB[cur];
#pragma unroll
        for (int ks = 0; ks < 2; ks++) {
            unsigned af[4][4], bf8[8][2];
#pragma unroll
            for (int mi = 0; mi < 4; mi++) {
                int mb = wm + mi * 16 + grp;
                af[mi][0] = sa[(ks * 8 + tig) * LDA + mb];
                af[mi][1] = sa[(ks * 8 + tig) * LDA + mb + 8];
                af[mi][2] = sa[(ks * 8 + tig + 4) * LDA + mb];
                af[mi][3] = sa[(ks * 8 + tig + 4) * LDA + mb + 8];
            }
#pragma unroll
            for (int ni = 0; ni < 8; ni++) {
                int nb = wn + ni * 8 + grp;
                bf8[ni][0] = sb[(ks * 8 + tig) * LDA + nb];
                bf8[ni][1] = sb[(ks * 8 + tig + 4) * LDA + nb];
            }
#pragma unroll
            for (int mi = 0; mi < 4; mi++)
#pragma unroll
                for (int ni = 0; ni < 8; ni++) mma8(acc[mi][ni], af[mi], bf8[ni]);
        }
        if (it + 1 < NIT) sts(cur ^ 1);
        __syncthreads();
    }

    float* S = attn + (size_t)z * APH;
    const float scale = 0.125f;  // 1/sqrt(64)
#pragma unroll
    for (int mi = 0; mi < 4; mi++) {
        int row = q0 + wm + mi * 16 + grp;
#pragma unroll
        for (int ni = 0; ni < 8; ni++) {
            int col = n0 + wn + ni * 8 + 2 * tig;
            S[(size_t)row * SEQ + col]           = acc[mi][ni][0] * scale;
            S[(size_t)row * SEQ + col + 1]       = acc[mi][ni][1] * scale;
            S[(size_t)(row + 8) * SEQ + col]     = acc[mi][ni][2] * scale;
            S[(size_t)(row + 8) * SEQ + col + 1] = acc[mi][ni][3] * scale;
        }
    }
}

// ======================================================================
// Softmax over rows of 2048, register-resident (1 read + 1 write)
// ======================================================================
__global__ __launch_bounds__(256) void softmax_rows(float* __restrict__ attn) {
    size_t row = blockIdx.x;
    float4* p = (float4*)(attn + row * (size_t)SEQ);
    int t = threadIdx.x, lane = t & 31, w = t >> 5;
    __shared__ float red[8];

    float4 v0 = p[t];
    float4 v1 = p[t + 256];

    float m = fmaxf(fmaxf(fmaxf(v0.x, v0.y), fmaxf(v0.z, v0.w)),
                    fmaxf(fmaxf(v1.x, v1.y), fmaxf(v1.z, v1.w)));
#pragma unroll
    for (int o = 16; o; o >>= 1) m = fmaxf(m, __shfl_xor_sync(~0u, m, o));
    if (lane == 0) red[w] = m;
    __syncthreads();
    m = red[0];
#pragma unroll
    for (int i = 1; i < 8; i++) m = fmaxf(m, red[i]);
    __syncthreads();

    v0.x = __expf(v0.x - m); v0.y = __expf(v0.y - m);
    v0.z = __expf(v0.z - m); v0.w = __expf(v0.w - m);
    v1.x = __expf(v1.x - m); v1.y = __expf(v1.y - m);
    v1.z = __expf(v1.z - m); v1.w = __expf(v1.w - m);

    float s = v0.x + v0.y + v0.z + v0.w + v1.x + v1.y + v1.z + v1.w;
#pragma unroll
    for (int o = 16; o; o >>= 1) s += __shfl_xor_sync(~0u, s, o);
    if (lane == 0) red[w] = s;
    __syncthreads();
    s = red[0];
#pragma unroll
    for (int i = 1; i < 8; i++) s += red[i];
    float inv = 1.f / s;

    v0.x *= inv; v0.y *= inv; v0.z *= inv; v0.w *= inv;
    v1.x *= inv; v1.y *= inv; v1.z *= inv; v1.w *= inv;
    p[t] = v0;
    p[t + 256] = v1;
}

// ======================================================================
// AV: ctx[b,q,h*64+n] = attn[z,q,:] @ V[b,:,h*64+n]    tile 128x64, K=2048
// (8 warps, 32x32 warp tiles — unchanged from the 1116us build)
// ======================================================================
__global__ __launch_bounds__(256) void av_tc(
    const float* __restrict__ attn, const float* __restrict__ V,
    float* __restrict__ ctx)
{
    __shared__ unsigned sA[2][PBK * LDA];
    __shared__ unsigned sB[2][PBK * LDBV];

    int tid = threadIdx.x, lane = tid & 31, wid = tid >> 5;
    int grp = lane >> 2, tig = lane & 3;
    int m0 = blockIdx.x * 128;
    int z = blockIdx.y, b = z / NHEADS, h = z % NHEADS;
    int wm = (wid >> 1) * 32, wn = (wid & 1) * 32;  // 4x2 warp grid, 32x32 tiles
    int ar = tid >> 2, ac = (tid & 3) * 4;          // A tile 128x16
    int rv = tid >> 4, cv = (tid & 15) * 4;         // V tile 16x64

    const float* Ab = attn + (size_t)z * APH;
    const float* Vb = V + (size_t)b * SEQ * DMODEL + h * HDIM;

    float acc[2][4][4] = {};
    float4 ra[2], rb;

    auto ldg = [&](int k0) {
        ra[0] = *(const float4*)&Ab[(size_t)(m0 + ar) * SEQ + k0 + ac];
        ra[1] = *(const float4*)&Ab[(size_t)(m0 + ar + 64) * SEQ + k0 + ac];
        rb    = *(const float4*)&Vb[(size_t)(k0 + rv) * DMODEL + cv];
    };
    auto sts = [&](int bf) {
        unsigned* pa = sA[bf];
        unsigned* pb = sB[bf];
#pragma unroll
        for (int p = 0; p < 2; p++) {
            const float* f = (const float*)&ra[p];
#pragma unroll
            for (int j = 0; j < 4; j++)
                pa[(ac + j) * LDA + ar + p * 64] = f2t(f[j]);
        }
        const float* g = (const float*)&rb;
#pragma unroll
        for (int j = 0; j < 4; j++) pb[rv * LDBV + cv + j] = f2t(g[j]);
    };

    const int NIT = SEQ / PBK;  // 128
    ldg(0);
    sts(0);
    __syncthreads();

    for (int it = 0; it < NIT; ++it) {
        int cur = it & 1;
        if (it + 1 < NIT) ldg((it + 1) * PBK);
        const unsigned* sa = sA[cur];
        const unsigned* sb = sB[cur];
#pragma unroll
        for (int ks = 0; ks < 2; ks++) {
            unsigned af[2][4], bf4[4][2];
#pragma unroll
            for (int mi = 0; mi < 2; mi++) {
                int mb = wm + mi * 16 + grp;
                af[mi][0] = sa[(ks * 8 + tig) * LDA + mb];
                af[mi][1] = sa[(ks * 8 + tig) * LDA + mb + 8];
                af[mi][2] = sa[(ks * 8 + tig + 4) * LDA + mb];
                af[mi][3] = sa[(ks * 8 + tig + 4) * LDA + mb + 8];
            }
#pragma unroll
            for (int ni = 0; ni < 4; ni++) {
                int nb = wn + ni * 8 + grp;
                bf4[ni][0] = sb[(ks * 8 + tig) * LDBV + nb];
                bf4[ni][1] = sb[(ks * 8 + tig + 4) * LDBV + nb];
            }
#pragma unroll
            for (int mi = 0; mi < 2; mi++)
#pragma unroll
                for (int ni = 0; ni < 4; ni++) mma8(acc[mi][ni], af[mi], bf4[ni]);
        }
        if (it + 1 < NIT) sts(cur ^ 1);
        __syncthreads();
    }

    float* Cb = ctx + (size_t)b * SEQ * DMODEL + h * HDIM;
#pragma unroll
    for (int mi = 0; mi < 2; mi++) {
        int row = m0 + wm + mi * 16 + grp;
#pragma unroll
        for (int ni = 0; ni < 4; ni++) {
            int col = wn + ni * 8 + 2 * tig;
            Cb[(size_t)row * DMODEL + col]           = acc[mi][ni][0];
            Cb[(size_t)row * DMODEL + col + 1]       = acc[mi][ni][1];
            Cb[(size_t)(row + 8) * DMODEL + col]     = acc[mi][ni][2];
            Cb[(size_t)(row + 8) * DMODEL + col + 1] = acc[mi][ni][3];
        }
    }
}

extern "C" void kernel_launch(void* const* d_in, const int* in_sizes, int n_in,
                              void* d_out, int out_size) {
    const float* x   = (const float*)d_in[0];
    const float* w_q = (const float*)d_in[1];
    const float* b_q = (const float*)d_in[2];
    const float* w_k = (const float*)d_in[3];
    const float* b_k = (const float*)d_in[4];
    const float* w_v = (const float*)d_in[5];
    const float* b_v = (const float*)d_in[6];
    const float* w_o = (const float*)d_in[7];
    const float* b_o = (const float*)d_in[8];

    float* out  = (float*)d_out;
    float* attn = out + OUT_ELEMS;

    float *q, *k, *v, *ctx;
    cudaGetSymbolAddress((void**)&q,   g_q);
    cudaGetSymbolAddress((void**)&k,   g_k);
    cudaGetSymbolAddress((void**)&v,   g_v);
    cudaGetSymbolAddress((void**)&ctx, g_ctx);

    // Fused QKV projections: one launch, z selects weight/bias/output
    GemmArgs qkv;
    qkv.A = x;
    qkv.W[0] = w_q; qkv.W[1] = w_k; qkv.W[2] = w_v;
    qkv.bias[0] = b_q; qkv.bias[1] = b_k; qkv.bias[2] = b_v;
    qkv.C[0] = q; qkv.C[1] = k; qkv.C[2] = v;
    dim3 g1(DMODEL / 128, MTOT / 128, 3);
    gemm3_tc<<<g1, 128>>>(qkv, MTOT, DMODEL, DMODEL);

    // Scores per (b,h): 2048x2048 = QK^T * scale
    dim3 g2(SEQ / 128, SEQ / 128, BATCH * NHEADS);
    scores_tc<<<g2, 128>>>(q, k, attn);

    // Softmax over rows (register-resident)
    softmax_rows<<<BATCH * NHEADS * SEQ, 256>>>(attn);

    // ctx = attn @ V
    dim3 g3(SEQ / 128, BATCH * NHEADS);
    av_tc<<<g3, 256>>>(attn, v, ctx);

    // out = ctx @ w_o + b_o
    GemmArgs op;
    op.A = ctx;
    op.W[0] = w_o; op.W[1] = w_o; op.W[2] = w_o;
    op.bias[0] = b_o; op.bias[1] = b_o; op.bias[2] = b_o;
    op.C[0] = out; op.C[1] = out; op.C[2] = out;
    dim3 g4(DMODEL / 128, MTOT / 128, 1);
    gemm3_tc<<<g4, 128>>>(op, MTOT, DMODEL, DMODEL);
}

// round 9
// speedup vs baseline: 1.7774x; 1.0787x over previous
#include <cuda_runtime.h>
#include <math.h>

// Problem constants
#define BATCH 2
#define SEQ 2048
#define DMODEL 1024
#define NHEADS 16
#define HDIM 64
#define MTOT (BATCH * SEQ)                 // 4096
#define OUT_ELEMS ((size_t)MTOT * DMODEL)  // 4,194,304
#define APH ((size_t)SEQ * SEQ)            // per-head attn elems

// Scratch (allocation-free rule: __device__ globals)
__device__ float g_q[MTOT * DMODEL];
__device__ float g_k[MTOT * DMODEL];
__device__ float g_v[MTOT * DMODEL];
__device__ float g_ctx[MTOT * DMODEL];

// ---------- tf32 helpers ----------
__device__ __forceinline__ unsigned f2t(float x) {
    unsigned u;
    asm("cvt.rna.tf32.f32 %0, %1;" : "=r"(u) : "f"(x));
    return u;
}

__device__ __forceinline__ void mma8(float* d, const unsigned* a, const unsigned* b) {
    asm volatile(
        "mma.sync.aligned.m16n8k8.row.col.f32.tf32.tf32.f32 "
        "{%0,%1,%2,%3}, {%4,%5,%6,%7}, {%8,%9}, {%0,%1,%2,%3};\n"
        : "+f"(d[0]), "+f"(d[1]), "+f"(d[2]), "+f"(d[3])
        : "r"(a[0]), "r"(a[1]), "r"(a[2]), "r"(a[3]), "r"(b[0]), "r"(b[1]));
}

#define LDA 132     // 128 + 4 pad (k-major smem row stride, words)
#define LDA256 260  // 256 + 4 pad for AV's 256-row A tile
#define LDBV 68     // 64 + 4 pad for AV's V tile
#define PBK 16      // K-chunk per smem stage

struct GemmArgs {
    const float* A;
    const float* W[3];
    const float* bias[3];
    float* C[3];
};

// ======================================================================
// GEMM: C[z][M,N] = A[M,K] @ W[z][K,N] + bias[z][N]
// CTA tile 128x128x16, 4 warps, warp tile 64x64 (2x2 warp grid)
// ======================================================================
__global__ __launch_bounds__(128) void gemm3_tc(GemmArgs ga, int M, int N, int K)
{
    __shared__ unsigned sA[2][PBK * LDA];
    __shared__ unsigned sB[2][PBK * LDA];

    int tid = threadIdx.x, lane = tid & 31, wid = tid >> 5;
    int grp = lane >> 2, tig = lane & 3;
    int m0 = blockIdx.y * 128, n0 = blockIdx.x * 128;
    int z = blockIdx.z;
    const float* A = ga.A;
    const float* B = ga.W[z];
    const float* bias = ga.bias[z];
    float* C = ga.C[z];

    int wm = (wid >> 1) * 64, wn = (wid & 1) * 64;
    int ar = tid >> 2, ac = (tid & 3) * 4;   // A tile rows 0..31 (+p*32), k cols
    int br = tid >> 5, bc = (tid & 31) * 4;  // B tile k-rows 0..3 (+p*4), n cols

    float acc[4][8][4] = {};
    float4 ra[4], rb[4];

    auto ldg = [&](int k0) {
#pragma unroll
        for (int p = 0; p < 4; p++) {
            ra[p] = *(const float4*)&A[(size_t)(m0 + ar + p * 32) * K + k0 + ac];
            rb[p] = *(const float4*)&B[(size_t)(k0 + br + p * 4) * N + n0 + bc];
        }
    };
    auto sts = [&](int bf) {
        unsigned* pa = sA[bf];
        unsigned* pb = sB[bf];
#pragma unroll
        for (int p = 0; p < 4; p++) {
            const float* f = (const float*)&ra[p];
            const float* g = (const float*)&rb[p];
#pragma unroll
            for (int j = 0; j < 4; j++) {
                pa[(ac + j) * LDA + ar + p * 32] = f2t(f[j]);   // k-major (transposed)
                pb[(br + p * 4) * LDA + bc + j] = f2t(g[j]);    // k-major (direct)
            }
        }
    };

    int NIT = K / PBK;
    ldg(0);
    sts(0);
    __syncthreads();

    for (int it = 0; it < NIT; ++it) {
        int cur = it & 1;
        if (it + 1 < NIT) ldg((it + 1) * PBK);
        const unsigned* sa = sA[cur];
        const unsigned* sb = sB[cur];
#pragma unroll
        for (int ks = 0; ks < 2; ks++) {
            unsigned af[4][4], bf8[8][2];
#pragma unroll
            for (int mi = 0; mi < 4; mi++) {
                int mb = wm + mi * 16 + grp;
                af[mi][0] = sa[(ks * 8 + tig) * LDA + mb];
                af[mi][1] = sa[(ks * 8 + tig) * LDA + mb + 8];
                af[mi][2] = sa[(ks * 8 + tig + 4) * LDA + mb];
                af[mi][3] = sa[(ks * 8 + tig + 4) * LDA + mb + 8];
            }
#pragma unroll
            for (int ni = 0; ni < 8; ni++) {
                int nb = wn + ni * 8 + grp;
                bf8[ni][0] = sb[(ks * 8 + tig) * LDA + nb];
                bf8[ni][1] = sb[(ks * 8 + tig + 4) * LDA + nb];
            }
#pragma unroll
            for (int mi = 0; mi < 4; mi++)
#pragma unroll
                for (int ni = 0; ni < 8; ni++) mma8(acc[mi][ni], af[mi], bf8[ni]);
        }
        if (it + 1 < NIT) sts(cur ^ 1);
        __syncthreads();
    }

#pragma unroll
    for (int mi = 0; mi < 4; mi++) {
        int row = m0 + wm + mi * 16 + grp;
#pragma unroll
        for (int ni = 0; ni < 8; ni++) {
            int col = n0 + wn + ni * 8 + 2 * tig;
            float b0 = bias[col], b1 = bias[col + 1];
            C[(size_t)row * N + col]           = acc[mi][ni][0] + b0;
            C[(size_t)row * N + col + 1]       = acc[mi][ni][1] + b1;
            C[(size_t)(row + 8) * N + col]     = acc[mi][ni][2] + b0;
            C[(size_t)(row + 8) * N + col + 1] = acc[mi][ni][3] + b1;
        }
    }
}

// ======================================================================
// Scores: attn[z,q,k] = (Q_z @ K_z^T) * 0.125
// CTA tile 128x128, K=64; 4 warps, warp tile 64x64
// ======================================================================
__global__ __launch_bounds__(128) void scores_tc(
    const float* __restrict__ Q, const float* __restrict__ Km,
    float* __restrict__ attn)
{
    __shared__ unsigned sA[2][PBK * LDA];
    __shared__ unsigned sB[2][PBK * LDA];

    int tid = threadIdx.x, lane = tid & 31, wid = tid >> 5;
    int grp = lane >> 2, tig = lane & 3;
    int q0 = blockIdx.y * 128, n0 = blockIdx.x * 128;
    int z = blockIdx.z, b = z / NHEADS, h = z % NHEADS;
    int wm = (wid >> 1) * 64, wn = (wid & 1) * 64;
    int ar = tid >> 2, ac = (tid & 3) * 4;

    const float* Qb = Q + (size_t)b * SEQ * DMODEL + h * HDIM;
    const float* Kb = Km + (size_t)b * SEQ * DMODEL + h * HDIM;

    float acc[4][8][4] = {};
    float4 ra[4], rk[4];

    auto ldg = [&](int k0) {
#pragma unroll
        for (int p = 0; p < 4; p++) {
            ra[p] = *(const float4*)&Qb[(size_t)(q0 + ar + p * 32) * DMODEL + k0 + ac];
            rk[p] = *(const float4*)&Kb[(size_t)(n0 + ar + p * 32) * DMODEL + k0 + ac];
        }
    };
    auto sts = [&](int bf) {
        unsigned* pa = sA[bf];
        unsigned* pb = sB[bf];
#pragma unroll
        for (int p = 0; p < 4; p++) {
            const float* f = (const float*)&ra[p];
            const float* g = (const float*)&rk[p];
#pragma unroll
            for (int j = 0; j < 4; j++) {
                pa[(ac + j) * LDA + ar + p * 32] = f2t(f[j]);
                pb[(ac + j) * LDA + ar + p * 32] = f2t(g[j]);
            }
        }
    };

    const int NIT = HDIM / PBK;  // 4
    ldg(0);
    sts(0);
    __syncthreads();

    for (int it = 0; it < NIT; ++it) {
        int cur = it & 1;
        if (it + 1 < NIT) ldg((it + 1) * PBK);
        const unsigned* sa = sA[cur];
        const unsigned* sb = sB[cur];
#pragma unroll
        for (int ks = 0; ks < 2; ks++) {
            unsigned af[4][4], bf8[8][2];
#pragma unroll
            for (int mi = 0; mi < 4; mi++) {
                int mb = wm + mi * 16 + grp;
                af[mi][0] = sa[(ks * 8 + tig) * LDA + mb];
                af[mi][1] = sa[(ks * 8 + tig) * LDA + mb + 8];
                af[mi][2] = sa[(ks * 8 + tig + 4) * LDA + mb];
                af[mi][3] = sa[(ks * 8 + tig + 4) * LDA + mb + 8];
            }
#pragma unroll
            for (int ni = 0; ni < 8; ni++) {
                int nb = wn + ni * 8 + grp;
                bf8[ni][0] = sb[(ks * 8 + tig) * LDA + nb];
                bf8[ni][1] = sb[(ks * 8 + tig + 4) * LDA + nb];
            }
#pragma unroll
            for (int mi = 0; mi < 4; mi++)
#pragma unroll
                for (int ni = 0; ni < 8; ni++) mma8(acc[mi][ni], af[mi], bf8[ni]);
        }
        if (it + 1 < NIT) sts(cur ^ 1);
        __syncthreads();
    }

    float* S = attn + (size_t)z * APH;
    const float scale = 0.125f;  // 1/sqrt(64)
#pragma unroll
    for (int mi = 0; mi < 4; mi++) {
        int row = q0 + wm + mi * 16 + grp;
#pragma unroll
        for (int ni = 0; ni < 8; ni++) {
            int col = n0 + wn + ni * 8 + 2 * tig;
            S[(size_t)row * SEQ + col]           = acc[mi][ni][0] * scale;
            S[(size_t)row * SEQ + col + 1]       = acc[mi][ni][1] * scale;
            S[(size_t)(row + 8) * SEQ + col]     = acc[mi][ni][2] * scale;
            S[(size_t)(row + 8) * SEQ + col + 1] = acc[mi][ni][3] * scale;
        }
    }
}

// ======================================================================
// Softmax over rows of 2048, register-resident (1 read + 1 write)
// ======================================================================
__global__ __launch_bounds__(256) void softmax_rows(float* __restrict__ attn) {
    size_t row = blockIdx.x;
    float4* p = (float4*)(attn + row * (size_t)SEQ);
    int t = threadIdx.x, lane = t & 31, w = t >> 5;
    __shared__ float red[8];

    float4 v0 = p[t];
    float4 v1 = p[t + 256];

    float m = fmaxf(fmaxf(fmaxf(v0.x, v0.y), fmaxf(v0.z, v0.w)),
                    fmaxf(fmaxf(v1.x, v1.y), fmaxf(v1.z, v1.w)));
#pragma unroll
    for (int o = 16; o; o >>= 1) m = fmaxf(m, __shfl_xor_sync(~0u, m, o));
    if (lane == 0) red[w] = m;
    __syncthreads();
    m = red[0];
#pragma unroll
    for (int i = 1; i < 8; i++) m = fmaxf(m, red[i]);
    __syncthreads();

    v0.x = __expf(v0.x - m); v0.y = __expf(v0.y - m);
    v0.z = __expf(v0.z - m); v0.w = __expf(v0.w - m);
    v1.x = __expf(v1.x - m); v1.y = __expf(v1.y - m);
    v1.z = __expf(v1.z - m); v1.w = __expf(v1.w - m);

    float s = v0.x + v0.y + v0.z + v0.w + v1.x + v1.y + v1.z + v1.w;
#pragma unroll
    for (int o = 16; o; o >>= 1) s += __shfl_xor_sync(~0u, s, o);
    if (lane == 0) red[w] = s;
    __syncthreads();
    s = red[0];
#pragma unroll
    for (int i = 1; i < 8; i++) s += red[i];
    float inv = 1.f / s;

    v0.x *= inv; v0.y *= inv; v0.z *= inv; v0.w *= inv;
    v1.x *= inv; v1.y *= inv; v1.z *= inv; v1.w *= inv;
    p[t] = v0;
    p[t + 256] = v1;
}

// ======================================================================
// AV: ctx[b,q,h*64+n] = attn[z,q,:] @ V[b,:,h*64+n]
// CTA tile 256x64, K=2048; 4 warps, warp tile 64x64 (warps split M)
// ======================================================================
__global__ __launch_bounds__(128) void av_tc(
    const float* __restrict__ attn, const float* __restrict__ V,
    float* __restrict__ ctx)
{
    __shared__ unsigned sA[2][PBK * LDA256];
    __shared__ unsigned sB[2][PBK * LDBV];

    int tid = threadIdx.x, lane = tid & 31, wid = tid >> 5;
    int grp = lane >> 2, tig = lane & 3;
    int m0 = blockIdx.x * 256;
    int z = blockIdx.y, b = z / NHEADS, h = z % NHEADS;
    int wm = wid * 64;                       // warps split M; all share N=64
    int ar = tid >> 2, ac = (tid & 3) * 4;   // A tile: rows 0..31 (+p*32), k cols
    int rv = tid >> 4, cv = (tid & 15) * 4;  // V tile: k-rows 0..7 (+p*8), n cols

    const float* Ab = attn + (size_t)z * APH;
    const float* Vb = V + (size_t)b * SEQ * DMODEL + h * HDIM;

    float acc[4][8][4] = {};
    float4 ra[8], rb[2];

    auto ldg = [&](int k0) {
#pragma unroll
        for (int p = 0; p < 8; p++)
            ra[p] = *(const float4*)&Ab[(size_t)(m0 + ar + p * 32) * SEQ + k0 + ac];
#pragma unroll
        for (int p = 0; p < 2; p++)
            rb[p] = *(const float4*)&Vb[(size_t)(k0 + rv + p * 8) * DMODEL + cv];
    };
    auto sts = [&](int bf) {
        unsigned* pa = sA[bf];
        unsigned* pb = sB[bf];
#pragma unroll
        for (int p = 0; p < 8; p++) {
            const float* f = (const float*)&ra[p];
#pragma unroll
            for (int j = 0; j < 4; j++)
                pa[(ac + j) * LDA256 + ar + p * 32] = f2t(f[j]);  // k-major
        }
#pragma unroll
        for (int p = 0; p < 2; p++) {
            const float* g = (const float*)&rb[p];
#pragma unroll
            for (int j = 0; j < 4; j++)
                pb[(rv + p * 8) * LDBV + cv + j] = f2t(g[j]);
        }
    };

    const int NIT = SEQ / PBK;  // 128
    ldg(0);
    sts(0);
    __syncthreads();

    for (int it = 0; it < NIT; ++it) {
        int cur = it & 1;
        if (it + 1 < NIT) ldg((it + 1) * PBK);
        const unsigned* sa = sA[cur];
        const unsigned* sb = sB[cur];
#pragma unroll
        for (int ks = 0; ks < 2; ks++) {
            unsigned af[4][4], bf8[8][2];
#pragma unroll
            for (int mi = 0; mi < 4; mi++) {
                int mb = wm + mi * 16 + grp;
                af[mi][0] = sa[(ks * 8 + tig) * LDA256 + mb];
                af[mi][1] = sa[(ks * 8 + tig) * LDA256 + mb + 8];
                af[mi][2] = sa[(ks * 8 + tig + 4) * LDA256 + mb];
                af[mi][3] = sa[(ks * 8 + tig + 4) * LDA256 + mb + 8];
            }
#pragma unroll
            for (int ni = 0; ni < 8; ni++) {
                int nb = ni * 8 + grp;
                bf8[ni][0] = sb[(ks * 8 + tig) * LDBV + nb];
                bf8[ni][1] = sb[(ks * 8 + tig + 4) * LDBV + nb];
            }
#pragma unroll
            for (int mi = 0; mi < 4; mi++)
#pragma unroll
                for (int ni = 0; ni < 8; ni++) mma8(acc[mi][ni], af[mi], bf8[ni]);
        }
        if (it + 1 < NIT) sts(cur ^ 1);
        __syncthreads();
    }

    float* Cb = ctx + (size_t)b * SEQ * DMODEL + h * HDIM;
#pragma unroll
    for (int mi = 0; mi < 4; mi++) {
        int row = m0 + wm + mi * 16 + grp;
#pragma unroll
        for (int ni = 0; ni < 8; ni++) {
            int col = ni * 8 + 2 * tig;
            Cb[(size_t)row * DMODEL + col]           = acc[mi][ni][0];
            Cb[(size_t)row * DMODEL + col + 1]       = acc[mi][ni][1];
            Cb[(size_t)(row + 8) * DMODEL + col]     = acc[mi][ni][2];
            Cb[(size_t)(row + 8) * DMODEL + col + 1] = acc[mi][ni][3];
        }
    }
}

extern "C" void kernel_launch(void* const* d_in, const int* in_sizes, int n_in,
                              void* d_out, int out_size) {
    const float* x   = (const float*)d_in[0];
    const float* w_q = (const float*)d_in[1];
    const float* b_q = (const float*)d_in[2];
    const float* w_k = (const float*)d_in[3];
    const float* b_k = (const float*)d_in[4];
    const float* w_v = (const float*)d_in[5];
    const float* b_v = (const float*)d_in[6];
    const float* w_o = (const float*)d_in[7];
    const float* b_o = (const float*)d_in[8];

    float* out  = (float*)d_out;
    float* attn = out + OUT_ELEMS;

    float *q, *k, *v, *ctx;
    cudaGetSymbolAddress((void**)&q,   g_q);
    cudaGetSymbolAddress((void**)&k,   g_k);
    cudaGetSymbolAddress((void**)&v,   g_v);
    cudaGetSymbolAddress((void**)&ctx, g_ctx);

    // Fused QKV projections: one launch, z selects weight/bias/output
    GemmArgs qkv;
    qkv.A = x;
    qkv.W[0] = w_q; qkv.W[1] = w_k; qkv.W[2] = w_v;
    qkv.bias[0] = b_q; qkv.bias[1] = b_k; qkv.bias[2] = b_v;
    qkv.C[0] = q; qkv.C[1] = k; qkv.C[2] = v;
    dim3 g1(DMODEL / 128, MTOT / 128, 3);
    gemm3_tc<<<g1, 128>>>(qkv, MTOT, DMODEL, DMODEL);

    // Scores per (b,h): 2048x2048 = QK^T * scale
    dim3 g2(SEQ / 128, SEQ / 128, BATCH * NHEADS);
    scores_tc<<<g2, 128>>>(q, k, attn);

    // Softmax over rows (register-resident)
    softmax_rows<<<BATCH * NHEADS * SEQ, 256>>>(attn);

    // ctx = attn @ V   (256x64 CTA tiles)
    dim3 g3(SEQ / 256, BATCH * NHEADS);
    av_tc<<<g3, 128>>>(attn, v, ctx);

    // out = ctx @ w_o + b_o
    GemmArgs op;
    op.A = ctx;
    op.W[0] = w_o; op.W[1] = w_o; op.W[2] = w_o;
    op.bias[0] = b_o; op.bias[1] = b_o; op.bias[2] = b_o;
    op.C[0] = out; op.C[1] = out; op.C[2] = out;
    dim3 g4(DMODEL / 128, MTOT / 128, 1);
    gemm3_tc<<<g4, 128>>>(op, MTOT, DMODEL, DMODEL);
}

// round 10
// speedup vs baseline: 1.9494x; 1.0968x over previous
#include <cuda_runtime.h>
#include <math.h>

// Problem constants
#define BATCH 2
#define SEQ 2048
#define DMODEL 1024
#define NHEADS 16
#define HDIM 64
#define MTOT (BATCH * SEQ)                 // 4096
#define OUT_ELEMS ((size_t)MTOT * DMODEL)  // 4,194,304
#define APH ((size_t)SEQ * SEQ)            // per-head attn elems

// Scratch (allocation-free rule: __device__ globals)
__device__ float g_q[MTOT * DMODEL];
__device__ float g_k[MTOT * DMODEL];
__device__ float g_v[MTOT * DMODEL];
__device__ float g_ctx[MTOT * DMODEL];

// ---------- tf32 / cp.async helpers ----------
__device__ __forceinline__ unsigned f2t(float x) {
    unsigned u;
    asm("cvt.rna.tf32.f32 %0, %1;" : "=r"(u) : "f"(x));
    return u;
}

__device__ __forceinline__ void mma8(float* d, const unsigned* a, const unsigned* b) {
    asm volatile(
        "mma.sync.aligned.m16n8k8.row.col.f32.tf32.tf32.f32 "
        "{%0,%1,%2,%3}, {%4,%5,%6,%7}, {%8,%9}, {%0,%1,%2,%3};\n"
        : "+f"(d[0]), "+f"(d[1]), "+f"(d[2]), "+f"(d[3])
        : "r"(a[0]), "r"(a[1]), "r"(a[2]), "r"(a[3]), "r"(b[0]), "r"(b[1]));
}

__device__ __forceinline__ unsigned sptr(const void* p) {
    return (unsigned)__cvta_generic_to_shared(p);
}
#define CPA(dst, src) \
    asm volatile("cp.async.cg.shared.global [%0], [%1], 16;\n" :: "r"(dst), "l"(src))
#define CPC() asm volatile("cp.async.commit_group;\n")
#define CPW1() asm volatile("cp.async.wait_group 1;\n" ::: "memory")

#define PBK 16     // K-chunk per smem stage
#define LDM 20     // m-major A-tile row stride (16 + 4 pad), words
#define LDN 132    // k-major B-tile row stride (128 + 4 pad), words
#define LDV 68     // k-major V-tile row stride (64 + 4), words

struct GemmArgs {
    const float* A;
    const float* W[3];
    const float* bias[3];
    float* C[3];
};

// ======================================================================
// GEMM: C[z][M,N] = A[M,K] @ W[z][K,N] + bias[z][N]
// CTA 128x128x16, 4 warps (64x64 each), cp.async 3-stage
// smem: A m-major 128xLDM, B k-major 16xLDN
// ======================================================================
#define G_SA 2560   // 128*20 words per stage
#define G_SB 2112   // 16*132 words per stage

__global__ __launch_bounds__(128) void gemm3_tc(GemmArgs ga, int M, int N, int K)
{
    extern __shared__ float smem[];
    float* sAb = smem;              // 3 * G_SA
    float* sBb = smem + 3 * G_SA;   // 3 * G_SB

    int tid = threadIdx.x, lane = tid & 31, wid = tid >> 5;
    int grp = lane >> 2, tig = lane & 3;
    int m0 = blockIdx.y * 128, n0 = blockIdx.x * 128;
    int z = blockIdx.z;
    const float* A = ga.A;
    const float* B = ga.W[z];
    const float* bias = ga.bias[z];
    float* C = ga.C[z];

    int wm = (wid >> 1) * 64, wn = (wid & 1) * 64;
    int ar = tid >> 2, ac = (tid & 3) * 4;   // A: rows ar+p*32, k-cols ac..ac+3
    int br = tid >> 5, bc = (tid & 31) * 4;  // B: k-rows br+p*4, n-cols bc..bc+3

    float acc[4][8][4] = {};

    auto issue = [&](int s, int k0) {
        float* pa = sAb + s * G_SA;
        float* pb = sBb + s * G_SB;
#pragma unroll
        for (int p = 0; p < 4; p++) {
            CPA(sptr(pa + (ar + p * 32) * LDM + ac),
                &A[(size_t)(m0 + ar + p * 32) * K + k0 + ac]);
            CPA(sptr(pb + (br + p * 4) * LDN + bc),
                &B[(size_t)(k0 + br + p * 4) * N + n0 + bc]);
        }
    };

    int NIT = K / PBK;
    issue(0, 0); CPC();
    issue(1, PBK); CPC();

    for (int it = 0; it < NIT; ++it) {
        CPW1();
        __syncthreads();
        int nx = it + 2;
        if (nx < NIT) issue(nx % 3, nx * PBK);
        CPC();
        const float* sa = sAb + (it % 3) * G_SA;
        const float* sb = sBb + (it % 3) * G_SB;
#pragma unroll
        for (int ks = 0; ks < 2; ks++) {
            int kk = ks * 8 + tig;
            unsigned af[4][4], bf8[8][2];
#pragma unroll
            for (int mi = 0; mi < 4; mi++) {
                int mb = wm + mi * 16 + grp;
                af[mi][0] = f2t(sa[mb * LDM + kk]);
                af[mi][1] = f2t(sa[(mb + 8) * LDM + kk]);
                af[mi][2] = f2t(sa[mb * LDM + kk + 4]);
                af[mi][3] = f2t(sa[(mb + 8) * LDM + kk + 4]);
            }
#pragma unroll
            for (int ni = 0; ni < 8; ni++) {
                int nb = wn + ni * 8 + grp;
                bf8[ni][0] = f2t(sb[kk * LDN + nb]);
                bf8[ni][1] = f2t(sb[(kk + 4) * LDN + nb]);
            }
#pragma unroll
            for (int mi = 0; mi < 4; mi++)
#pragma unroll
                for (int ni = 0; ni < 8; ni++) mma8(acc[mi][ni], af[mi], bf8[ni]);
        }
    }

#pragma unroll
    for (int mi = 0; mi < 4; mi++) {
        int row = m0 + wm + mi * 16 + grp;
#pragma unroll
        for (int ni = 0; ni < 8; ni++) {
            int col = n0 + wn + ni * 8 + 2 * tig;
            float b0 = bias[col], b1 = bias[col + 1];
            C[(size_t)row * N + col]           = acc[mi][ni][0] + b0;
            C[(size_t)row * N + col + 1]       = acc[mi][ni][1] + b1;
            C[(size_t)(row + 8) * N + col]     = acc[mi][ni][2] + b0;
            C[(size_t)(row + 8) * N + col + 1] = acc[mi][ni][3] + b1;
        }
    }
}

// ======================================================================
// Scores: attn[z,q,k] = (Q_z @ K_z^T) * 0.125
// CTA 128x128, K=64; 4 warps (64x64); cp.async 3-stage, both tiles m-major
// ======================================================================
#define S_ST 2560   // 128*20 words per stage

__global__ __launch_bounds__(128) void scores_tc(
    const float* __restrict__ Q, const float* __restrict__ Km,
    float* __restrict__ attn)
{
    extern __shared__ float smem[];
    float* sAb = smem;             // 3 * S_ST (Q tile)
    float* sBb = smem + 3 * S_ST;  // 3 * S_ST (K tile)

    int tid = threadIdx.x, lane = tid & 31, wid = tid >> 5;
    int grp = lane >> 2, tig = lane & 3;
    int q0 = blockIdx.y * 128, n0 = blockIdx.x * 128;
    int z = blockIdx.z, b = z / NHEADS, h = z % NHEADS;
    int wm = (wid >> 1) * 64, wn = (wid & 1) * 64;
    int ar = tid >> 2, ac = (tid & 3) * 4;

    const float* Qb = Q + (size_t)b * SEQ * DMODEL + h * HDIM;
    const float* Kb = Km + (size_t)b * SEQ * DMODEL + h * HDIM;

    float acc[4][8][4] = {};

    auto issue = [&](int s, int k0) {
        float* pa = sAb + s * S_ST;
        float* pb = sBb + s * S_ST;
#pragma unroll
        for (int p = 0; p < 4; p++) {
            CPA(sptr(pa + (ar + p * 32) * LDM + ac),
                &Qb[(size_t)(q0 + ar + p * 32) * DMODEL + k0 + ac]);
            CPA(sptr(pb + (ar + p * 32) * LDM + ac),
                &Kb[(size_t)(n0 + ar + p * 32) * DMODEL + k0 + ac]);
        }
    };

    const int NIT = HDIM / PBK;  // 4
    issue(0, 0); CPC();
    issue(1, PBK); CPC();

    for (int it = 0; it < NIT; ++it) {
        CPW1();
        __syncthreads();
        int nx = it + 2;
        if (nx < NIT) issue(nx % 3, nx * PBK);
        CPC();
        const float* sa = sAb + (it % 3) * S_ST;
        const float* sb = sBb + (it % 3) * S_ST;
#pragma unroll
        for (int ks = 0; ks < 2; ks++) {
            int kk = ks * 8 + tig;
            unsigned af[4][4], bf8[8][2];
#pragma unroll
            for (int mi = 0; mi < 4; mi++) {
                int mb = wm + mi * 16 + grp;
                af[mi][0] = f2t(sa[mb * LDM + kk]);
                af[mi][1] = f2t(sa[(mb + 8) * LDM + kk]);
                af[mi][2] = f2t(sa[mb * LDM + kk + 4]);
                af[mi][3] = f2t(sa[(mb + 8) * LDM + kk + 4]);
            }
#pragma unroll
            for (int ni = 0; ni < 8; ni++) {
                int nb = wn + ni * 8 + grp;
                bf8[ni][0] = f2t(sb[nb * LDM + kk]);
                bf8[ni][1] = f2t(sb[nb * LDM + kk + 4]);
            }
#pragma unroll
            for (int mi = 0; mi < 4; mi++)
#pragma unroll
                for (int ni = 0; ni < 8; ni++) mma8(acc[mi][ni], af[mi], bf8[ni]);
        }
    }

    float* S = attn + (size_t)z * APH;
    const float scale = 0.125f;  // 1/sqrt(64)
#pragma unroll
    for (int mi = 0; mi < 4; mi++) {
        int row = q0 + wm + mi * 16 + grp;
#pragma unroll
        for (int ni = 0; ni < 8; ni++) {
            int col = n0 + wn + ni * 8 + 2 * tig;
            S[(size_t)row * SEQ + col]           = acc[mi][ni][0] * scale;
            S[(size_t)row * SEQ + col + 1]       = acc[mi][ni][1] * scale;
            S[(size_t)(row + 8) * SEQ + col]     = acc[mi][ni][2] * scale;
            S[(size_t)(row + 8) * SEQ + col + 1] = acc[mi][ni][3] * scale;
        }
    }
}

// ======================================================================
// Softmax over rows of 2048, register-resident (1 read + 1 write)
// ======================================================================
__global__ __launch_bounds__(256) void softmax_rows(float* __restrict__ attn) {
    size_t row = blockIdx.x;
    float4* p = (float4*)(attn + row * (size_t)SEQ);
    int t = threadIdx.x, lane = t & 31, w = t >> 5;
    __shared__ float red[8];

    float4 v0 = p[t];
    float4 v1 = p[t + 256];

    float m = fmaxf(fmaxf(fmaxf(v0.x, v0.y), fmaxf(v0.z, v0.w)),
                    fmaxf(fmaxf(v1.x, v1.y), fmaxf(v1.z, v1.w)));
#pragma unroll
    for (int o = 16; o; o >>= 1) m = fmaxf(m, __shfl_xor_sync(~0u, m, o));
    if (lane == 0) red[w] = m;
    __syncthreads();
    m = red[0];
#pragma unroll
    for (int i = 1; i < 8; i++) m = fmaxf(m, red[i]);
    __syncthreads();

    v0.x = __expf(v0.x - m); v0.y = __expf(v0.y - m);
    v0.z = __expf(v0.z - m); v0.w = __expf(v0.w - m);
    v1.x = __expf(v1.x - m); v1.y = __expf(v1.y - m);
    v1.z = __expf(v1.z - m); v1.w = __expf(v1.w - m);

    float s = v0.x + v0.y + v0.z + v0.w + v1.x + v1.y + v1.z + v1.w;
#pragma unroll
    for (int o = 16; o; o >>= 1) s += __shfl_xor_sync(~0u, s, o);
    if (lane == 0) red[w] = s;
    __syncthreads();
    s = red[0];
#pragma unroll
    for (int i = 1; i < 8; i++) s += red[i];
    float inv = 1.f / s;

    v0.x *= inv; v0.y *= inv; v0.z *= inv; v0.w *= inv;
    v1.x *= inv; v1.y *= inv; v1.z *= inv; v1.w *= inv;
    p[t] = v0;
    p[t + 256] = v1;
}

// ======================================================================
// AV: ctx[b,q,h*64+n] = attn[z,q,:] @ V[b,:,h*64+n]
// CTA 256x64, K=2048; 4 warps (64x64, M-split); cp.async 3-stage
// ======================================================================
#define V_SA 5120   // 256*20 words per stage
#define V_SB 1088   // 16*68 words per stage

__global__ __launch_bounds__(128) void av_tc(
    const float* __restrict__ attn, const float* __restrict__ V,
    float* __restrict__ ctx)
{
    extern __shared__ float smem[];
    float* sAb = smem;             // 3 * V_SA
    float* sBb = smem + 3 * V_SA;  // 3 * V_SB

    int tid = threadIdx.x, lane = tid & 31, wid = tid >> 5;
    int grp = lane >> 2, tig = lane & 3;
    int m0 = blockIdx.x * 256;
    int z = blockIdx.y, b = z / NHEADS, h = z % NHEADS;
    int wm = wid * 64;                       // warps split M; all share N=64
    int ar = tid >> 2, ac = (tid & 3) * 4;   // A: rows ar+p*32 (p<8), k-cols ac
    int rv = tid >> 4, cv = (tid & 15) * 4;  // V: k-rows rv+p*8 (p<2), n-cols cv

    const float* Ab = attn + (size_t)z * APH;
    const float* Vb = V + (size_t)b * SEQ * DMODEL + h * HDIM;

    float acc[4][8][4] = {};

    auto issue = [&](int s, int k0) {
        float* pa = sAb + s * V_SA;
        float* pb = sBb + s * V_SB;
#pragma unroll
        for (int p = 0; p < 8; p++)
            CPA(sptr(pa + (ar + p * 32) * LDM + ac),
                &Ab[(size_t)(m0 + ar + p * 32) * SEQ + k0 + ac]);
#pragma unroll
        for (int p = 0; p < 2; p++)
            CPA(sptr(pb + (rv + p * 8) * LDV + cv),
                &Vb[(size_t)(k0 + rv + p * 8) * DMODEL + cv]);
    };

    const int NIT = SEQ / PBK;  // 128
    issue(0, 0); CPC();
    issue(1, PBK); CPC();

    for (int it = 0; it < NIT; ++it) {
        CPW1();
        __syncthreads();
        int nx = it + 2;
        if (nx < NIT) issue(nx % 3, nx * PBK);
        CPC();
        const float* sa = sAb + (it % 3) * V_SA;
        const float* sb = sBb + (it % 3) * V_SB;
#pragma unroll
        for (int ks = 0; ks < 2; ks++) {
            int kk = ks * 8 + tig;
            unsigned af[4][4], bf8[8][2];
#pragma unroll
            for (int mi = 0; mi < 4; mi++) {
                int mb = wm + mi * 16 + grp;
                af[mi][0] = f2t(sa[mb * LDM + kk]);
                af[mi][1] = f2t(sa[(mb + 8) * LDM + kk]);
                af[mi][2] = f2t(sa[mb * LDM + kk + 4]);
                af[mi][3] = f2t(sa[(mb + 8) * LDM + kk + 4]);
            }
#pragma unroll
            for (int ni = 0; ni < 8; ni++) {
                int nb = ni * 8 + grp;
                bf8[ni][0] = f2t(sb[kk * LDV + nb]);
                bf8[ni][1] = f2t(sb[(kk + 4) * LDV + nb]);
            }
#pragma unroll
            for (int mi = 0; mi < 4; mi++)
#pragma unroll
                for (int ni = 0; ni < 8; ni++) mma8(acc[mi][ni], af[mi], bf8[ni]);
        }
    }

    float* Cb = ctx + (size_t)b * SEQ * DMODEL + h * HDIM;
#pragma unroll
    for (int mi = 0; mi < 4; mi++) {
        int row = m0 + wm + mi * 16 + grp;
#pragma unroll
        for (int ni = 0; ni < 8; ni++) {
            int col = ni * 8 + 2 * tig;
            Cb[(size_t)row * DMODEL + col]           = acc[mi][ni][0];
            Cb[(size_t)row * DMODEL + col + 1]       = acc[mi][ni][1];
            Cb[(size_t)(row + 8) * DMODEL + col]     = acc[mi][ni][2];
            Cb[(size_t)(row + 8) * DMODEL + col + 1] = acc[mi][ni][3];
        }
    }
}

extern "C" void kernel_launch(void* const* d_in, const int* in_sizes, int n_in,
                              void* d_out, int out_size) {
    const float* x   = (const float*)d_in[0];
    const float* w_q = (const float*)d_in[1];
    const float* b_q = (const float*)d_in[2];
    const float* w_k = (const float*)d_in[3];
    const float* b_k = (const float*)d_in[4];
    const float* w_v = (const float*)d_in[5];
    const float* b_v = (const float*)d_in[6];
    const float* w_o = (const float*)d_in[7];
    const float* b_o = (const float*)d_in[8];

    float* out  = (float*)d_out;
    float* attn = out + OUT_ELEMS;

    float *q, *k, *v, *ctx;
    cudaGetSymbolAddress((void**)&q,   g_q);
    cudaGetSymbolAddress((void**)&k,   g_k);
    cudaGetSymbolAddress((void**)&v,   g_v);
    cudaGetSymbolAddress((void**)&ctx, g_ctx);

    const int gemmSmem   = (3 * G_SA + 3 * G_SB) * 4;   // 56064 B
    const int scoresSmem = (6 * S_ST) * 4;              // 61440 B
    const int avSmem     = (3 * V_SA + 3 * V_SB) * 4;   // 74496 B
    cudaFuncSetAttribute(gemm3_tc,  cudaFuncAttributeMaxDynamicSharedMemorySize, gemmSmem);
    cudaFuncSetAttribute(scores_tc, cudaFuncAttributeMaxDynamicSharedMemorySize, scoresSmem);
    cudaFuncSetAttribute(av_tc,     cudaFuncAttributeMaxDynamicSharedMemorySize, avSmem);

    // Fused QKV projections: one launch, z selects weight/bias/output
    GemmArgs qkv;
    qkv.A = x;
    qkv.W[0] = w_q; qkv.W[1] = w_k; qkv.W[2] = w_v;
    qkv.bias[0] = b_q; qkv.bias[1] = b_k; qkv.bias[2] = b_v;
    qkv.C[0] = q; qkv.C[1] = k; qkv.C[2] = v;
    dim3 g1(DMODEL / 128, MTOT / 128, 3);
    gemm3_tc<<<g1, 128, gemmSmem>>>(qkv, MTOT, DMODEL, DMODEL);

    // Scores per (b,h): 2048x2048 = QK^T * scale
    dim3 g2(SEQ / 128, SEQ / 128, BATCH * NHEADS);
    scores_tc<<<g2, 128, scoresSmem>>>(q, k, attn);

    // Softmax over rows (register-resident)
    softmax_rows<<<BATCH * NHEADS * SEQ, 256>>>(attn);

    // ctx = attn @ V   (256x64 CTA tiles)
    dim3 g3(SEQ / 256, BATCH * NHEADS);
    av_tc<<<g3, 128, avSmem>>>(attn, v, ctx);

    // out = ctx @ w_o + b_o
    GemmArgs op;
    op.A = ctx;
    op.W[0] = w_o; op.W[1] = w_o; op.W[2] = w_o;
    op.bias[0] = b_o; op.bias[1] = b_o; op.bias[2] = b_o;
    op.C[0] = out; op.C[1] = out; op.C[2] = out;
    dim3 g4(DMODEL / 128, MTOT / 128, 1);
    gemm3_tc<<<g4, 128, gemmSmem>>>(op, MTOT, DMODEL, DMODEL);
}

// round 11
// speedup vs baseline: 1.9540x; 1.0024x over previous
#include <cuda_runtime.h>
#include <math.h>

// Problem constants
#define BATCH 2
#define SEQ 2048
#define DMODEL 1024
#define NHEADS 16
#define HDIM 64
#define MTOT (BATCH * SEQ)                 // 4096
#define OUT_ELEMS ((size_t)MTOT * DMODEL)  // 4,194,304
#define APH ((size_t)SEQ * SEQ)            // per-head attn elems

// Scratch (allocation-free rule: __device__ globals)
__device__ float g_q[MTOT * DMODEL];
__device__ float g_k[MTOT * DMODEL];
__device__ float g_v[MTOT * DMODEL];
__device__ float g_ctx[MTOT * DMODEL];

// ---------- tf32 / cp.async helpers ----------
__device__ __forceinline__ unsigned f2t(float x) {
    unsigned u;
    asm("cvt.rna.tf32.f32 %0, %1;" : "=r"(u) : "f"(x));
    return u;
}

__device__ __forceinline__ void mma8(float* d, const unsigned* a, const unsigned* b) {
    asm volatile(
        "mma.sync.aligned.m16n8k8.row.col.f32.tf32.tf32.f32 "
        "{%0,%1,%2,%3}, {%4,%5,%6,%7}, {%8,%9}, {%0,%1,%2,%3};\n"
        : "+f"(d[0]), "+f"(d[1]), "+f"(d[2]), "+f"(d[3])
        : "r"(a[0]), "r"(a[1]), "r"(a[2]), "r"(a[3]), "r"(b[0]), "r"(b[1]));
}

__device__ __forceinline__ unsigned sptr(const void* p) {
    return (unsigned)__cvta_generic_to_shared(p);
}
#define CPA(dst, src) \
    asm volatile("cp.async.cg.shared.global [%0], [%1], 16;\n" :: "r"(dst), "l"(src))
#define CPC() asm volatile("cp.async.commit_group;\n")
#define CPW1() asm volatile("cp.async.wait_group 1;\n" ::: "memory")

#define PBK 16     // K-chunk per smem stage
#define LDM 20     // m-major A-tile row stride (16 + 4 pad), words
#define LDN 132    // k-major B-tile row stride (128 + 4 pad), words
#define LDV 68     // k-major V-tile row stride (64 + 4), words

struct GemmArgs {
    const float* A;
    const float* W[3];
    const float* bias[3];
    float* C[3];
};

// ======================================================================
// GEMM: C[z][M,N] = A[M,K] @ W[z][K,N] + bias[z][N]
// CTA 128x128x16, 4 warps (64x64 each), cp.async 3-stage
// ======================================================================
#define G_SA 2560   // 128*20 words per stage
#define G_SB 2112   // 16*132 words per stage

__global__ __launch_bounds__(128) void gemm3_tc(GemmArgs ga, int M, int N, int K)
{
    extern __shared__ float smem[];
    float* sAb = smem;              // 3 * G_SA
    float* sBb = smem + 3 * G_SA;   // 3 * G_SB

    int tid = threadIdx.x, lane = tid & 31, wid = tid >> 5;
    int grp = lane >> 2, tig = lane & 3;
    int m0 = blockIdx.y * 128, n0 = blockIdx.x * 128;
    int z = blockIdx.z;
    const float* A = ga.A;
    const float* B = ga.W[z];
    const float* bias = ga.bias[z];
    float* C = ga.C[z];

    int wm = (wid >> 1) * 64, wn = (wid & 1) * 64;
    int ar = tid >> 2, ac = (tid & 3) * 4;
    int br = tid >> 5, bc = (tid & 31) * 4;

    float acc[4][8][4] = {};

    auto issue = [&](int s, int k0) {
        float* pa = sAb + s * G_SA;
        float* pb = sBb + s * G_SB;
#pragma unroll
        for (int p = 0; p < 4; p++) {
            CPA(sptr(pa + (ar + p * 32) * LDM + ac),
                &A[(size_t)(m0 + ar + p * 32) * K + k0 + ac]);
            CPA(sptr(pb + (br + p * 4) * LDN + bc),
                &B[(size_t)(k0 + br + p * 4) * N + n0 + bc]);
        }
    };

    int NIT = K / PBK;
    issue(0, 0); CPC();
    issue(1, PBK); CPC();

    for (int it = 0; it < NIT; ++it) {
        CPW1();
        __syncthreads();
        int nx = it + 2;
        if (nx < NIT) issue(nx % 3, nx * PBK);
        CPC();
        const float* sa = sAb + (it % 3) * G_SA;
        const float* sb = sBb + (it % 3) * G_SB;
#pragma unroll
        for (int ks = 0; ks < 2; ks++) {
            int kk = ks * 8 + tig;
            unsigned af[4][4], bf8[8][2];
#pragma unroll
            for (int mi = 0; mi < 4; mi++) {
                int mb = wm + mi * 16 + grp;
                af[mi][0] = f2t(sa[mb * LDM + kk]);
                af[mi][1] = f2t(sa[(mb + 8) * LDM + kk]);
                af[mi][2] = f2t(sa[mb * LDM + kk + 4]);
                af[mi][3] = f2t(sa[(mb + 8) * LDM + kk + 4]);
            }
#pragma unroll
            for (int ni = 0; ni < 8; ni++) {
                int nb = wn + ni * 8 + grp;
                bf8[ni][0] = f2t(sb[kk * LDN + nb]);
                bf8[ni][1] = f2t(sb[(kk + 4) * LDN + nb]);
            }
#pragma unroll
            for (int mi = 0; mi < 4; mi++)
#pragma unroll
                for (int ni = 0; ni < 8; ni++) mma8(acc[mi][ni], af[mi], bf8[ni]);
        }
    }

#pragma unroll
    for (int mi = 0; mi < 4; mi++) {
        int row = m0 + wm + mi * 16 + grp;
#pragma unroll
        for (int ni = 0; ni < 8; ni++) {
            int col = n0 + wn + ni * 8 + 2 * tig;
            float b0 = bias[col], b1 = bias[col + 1];
            C[(size_t)row * N + col]           = acc[mi][ni][0] + b0;
            C[(size_t)row * N + col + 1]       = acc[mi][ni][1] + b1;
            C[(size_t)(row + 8) * N + col]     = acc[mi][ni][2] + b0;
            C[(size_t)(row + 8) * N + col + 1] = acc[mi][ni][3] + b1;
        }
    }
}

// ======================================================================
// Split-K GEMM (accumulate): C[M,N] += A[M,K-slice] @ B[K-slice,N]
// grid.z = K split index; C must be pre-initialized (bias).
// ======================================================================
__global__ __launch_bounds__(128) void gemm_split_tc(
    const float* __restrict__ A, const float* __restrict__ B,
    float* __restrict__ C, int M, int N, int K, int kLen)
{
    extern __shared__ float smem[];
    float* sAb = smem;
    float* sBb = smem + 3 * G_SA;

    int tid = threadIdx.x, lane = tid & 31, wid = tid >> 5;
    int grp = lane >> 2, tig = lane & 3;
    int m0 = blockIdx.y * 128, n0 = blockIdx.x * 128;
    int koff = blockIdx.z * kLen;

    int wm = (wid >> 1) * 64, wn = (wid & 1) * 64;
    int ar = tid >> 2, ac = (tid & 3) * 4;
    int br = tid >> 5, bc = (tid & 31) * 4;

    float acc[4][8][4] = {};

    auto issue = [&](int s, int k0) {
        float* pa = sAb + s * G_SA;
        float* pb = sBb + s * G_SB;
#pragma unroll
        for (int p = 0; p < 4; p++) {
            CPA(sptr(pa + (ar + p * 32) * LDM + ac),
                &A[(size_t)(m0 + ar + p * 32) * K + koff + k0 + ac]);
            CPA(sptr(pb + (br + p * 4) * LDN + bc),
                &B[(size_t)(koff + k0 + br + p * 4) * N + n0 + bc]);
        }
    };

    int NIT = kLen / PBK;
    issue(0, 0); CPC();
    issue(1, PBK); CPC();

    for (int it = 0; it < NIT; ++it) {
        CPW1();
        __syncthreads();
        int nx = it + 2;
        if (nx < NIT) issue(nx % 3, nx * PBK);
        CPC();
        const float* sa = sAb + (it % 3) * G_SA;
        const float* sb = sBb + (it % 3) * G_SB;
#pragma unroll
        for (int ks = 0; ks < 2; ks++) {
            int kk = ks * 8 + tig;
            unsigned af[4][4], bf8[8][2];
#pragma unroll
            for (int mi = 0; mi < 4; mi++) {
                int mb = wm + mi * 16 + grp;
                af[mi][0] = f2t(sa[mb * LDM + kk]);
                af[mi][1] = f2t(sa[(mb + 8) * LDM + kk]);
                af[mi][2] = f2t(sa[mb * LDM + kk + 4]);
                af[mi][3] = f2t(sa[(mb + 8) * LDM + kk + 4]);
            }
#pragma unroll
            for (int ni = 0; ni < 8; ni++) {
                int nb = wn + ni * 8 + grp;
                bf8[ni][0] = f2t(sb[kk * LDN + nb]);
                bf8[ni][1] = f2t(sb[(kk + 4) * LDN + nb]);
            }
#pragma unroll
            for (int mi = 0; mi < 4; mi++)
#pragma unroll
                for (int ni = 0; ni < 8; ni++) mma8(acc[mi][ni], af[mi], bf8[ni]);
        }
    }

#pragma unroll
    for (int mi = 0; mi < 4; mi++) {
        int row = m0 + wm + mi * 16 + grp;
#pragma unroll
        for (int ni = 0; ni < 8; ni++) {
            int col = n0 + wn + ni * 8 + 2 * tig;
            atomicAdd(&C[(size_t)row * N + col],           acc[mi][ni][0]);
            atomicAdd(&C[(size_t)row * N + col + 1],       acc[mi][ni][1]);
            atomicAdd(&C[(size_t)(row + 8) * N + col],     acc[mi][ni][2]);
            atomicAdd(&C[(size_t)(row + 8) * N + col + 1], acc[mi][ni][3]);
        }
    }
}

// ======================================================================
// Scores: attn[z,q,k] = (Q_z @ K_z^T) * 0.125
// ======================================================================
#define S_ST 2560   // 128*20 words per stage

__global__ __launch_bounds__(128) void scores_tc(
    const float* __restrict__ Q, const float* __restrict__ Km,
    float* __restrict__ attn)
{
    extern __shared__ float smem[];
    float* sAb = smem;
    float* sBb = smem + 3 * S_ST;

    int tid = threadIdx.x, lane = tid & 31, wid = tid >> 5;
    int grp = lane >> 2, tig = lane & 3;
    int q0 = blockIdx.y * 128, n0 = blockIdx.x * 128;
    int z = blockIdx.z, b = z / NHEADS, h = z % NHEADS;
    int wm = (wid >> 1) * 64, wn = (wid & 1) * 64;
    int ar = tid >> 2, ac = (tid & 3) * 4;

    const float* Qb = Q + (size_t)b * SEQ * DMODEL + h * HDIM;
    const float* Kb = Km + (size_t)b * SEQ * DMODEL + h * HDIM;

    float acc[4][8][4] = {};

    auto issue = [&](int s, int k0) {
        float* pa = sAb + s * S_ST;
        float* pb = sBb + s * S_ST;
#pragma unroll
        for (int p = 0; p < 4; p++) {
            CPA(sptr(pa + (ar + p * 32) * LDM + ac),
                &Qb[(size_t)(q0 + ar + p * 32) * DMODEL + k0 + ac]);
            CPA(sptr(pb + (ar + p * 32) * LDM + ac),
                &Kb[(size_t)(n0 + ar + p * 32) * DMODEL + k0 + ac]);
        }
    };

    const int NIT = HDIM / PBK;  // 4
    issue(0, 0); CPC();
    issue(1, PBK); CPC();

    for (int it = 0; it < NIT; ++it) {
        CPW1();
        __syncthreads();
        int nx = it + 2;
        if (nx < NIT) issue(nx % 3, nx * PBK);
        CPC();
        const float* sa = sAb + (it % 3) * S_ST;
        const float* sb = sBb + (it % 3) * S_ST;
#pragma unroll
        for (int ks = 0; ks < 2; ks++) {
            int kk = ks * 8 + tig;
            unsigned af[4][4], bf8[8][2];
#pragma unroll
            for (int mi = 0; mi < 4; mi++) {
                int mb = wm + mi * 16 + grp;
                af[mi][0] = f2t(sa[mb * LDM + kk]);
                af[mi][1] = f2t(sa[(mb + 8) * LDM + kk]);
                af[mi][2] = f2t(sa[mb * LDM + kk + 4]);
                af[mi][3] = f2t(sa[(mb + 8) * LDM + kk + 4]);
            }
#pragma unroll
            for (int ni = 0; ni < 8; ni++) {
                int nb = wn + ni * 8 + grp;
                bf8[ni][0] = f2t(sb[nb * LDM + kk]);
                bf8[ni][1] = f2t(sb[nb * LDM + kk + 4]);
            }
#pragma unroll
            for (int mi = 0; mi < 4; mi++)
#pragma unroll
                for (int ni = 0; ni < 8; ni++) mma8(acc[mi][ni], af[mi], bf8[ni]);
        }
    }

    float* S = attn + (size_t)z * APH;
    const float scale = 0.125f;  // 1/sqrt(64)
#pragma unroll
    for (int mi = 0; mi < 4; mi++) {
        int row = q0 + wm + mi * 16 + grp;
#pragma unroll
        for (int ni = 0; ni < 8; ni++) {
            int col = n0 + wn + ni * 8 + 2 * tig;
            S[(size_t)row * SEQ + col]           = acc[mi][ni][0] * scale;
            S[(size_t)row * SEQ + col + 1]       = acc[mi][ni][1] * scale;
            S[(size_t)(row + 8) * SEQ + col]     = acc[mi][ni][2] * scale;
            S[(size_t)(row + 8) * SEQ + col + 1] = acc[mi][ni][3] * scale;
        }
    }
}

// ======================================================================
// Softmax over rows of 2048, register-resident (1 read + 1 write)
// ======================================================================
__global__ __launch_bounds__(256) void softmax_rows(float* __restrict__ attn) {
    size_t row = blockIdx.x;
    float4* p = (float4*)(attn + row * (size_t)SEQ);
    int t = threadIdx.x, lane = t & 31, w = t >> 5;
    __shared__ float red[8];

    float4 v0 = p[t];
    float4 v1 = p[t + 256];

    float m = fmaxf(fmaxf(fmaxf(v0.x, v0.y), fmaxf(v0.z, v0.w)),
                    fmaxf(fmaxf(v1.x, v1.y), fmaxf(v1.z, v1.w)));
#pragma unroll
    for (int o = 16; o; o >>= 1) m = fmaxf(m, __shfl_xor_sync(~0u, m, o));
    if (lane == 0) red[w] = m;
    __syncthreads();
    m = red[0];
#pragma unroll
    for (int i = 1; i < 8; i++) m = fmaxf(m, red[i]);
    __syncthreads();

    v0.x = __expf(v0.x - m); v0.y = __expf(v0.y - m);
    v0.z = __expf(v0.z - m); v0.w = __expf(v0.w - m);
    v1.x = __expf(v1.x - m); v1.y = __expf(v1.y - m);
    v1.z = __expf(v1.z - m); v1.w = __expf(v1.w - m);

    float s = v0.x + v0.y + v0.z + v0.w + v1.x + v1.y + v1.z + v1.w;
#pragma unroll
    for (int o = 16; o; o >>= 1) s += __shfl_xor_sync(~0u, s, o);
    if (lane == 0) red[w] = s;
    __syncthreads();
    s = red[0];
#pragma unroll
    for (int i = 1; i < 8; i++) s += red[i];
    float inv = 1.f / s;

    v0.x *= inv; v0.y *= inv; v0.z *= inv; v0.w *= inv;
    v1.x *= inv; v1.y *= inv; v1.z *= inv; v1.w *= inv;
    p[t] = v0;
    p[t + 256] = v1;
}

// ======================================================================
// Init kernels (streaming)
// ======================================================================
__global__ __launch_bounds__(256) void zero_f4(float* __restrict__ p) {
    size_t i = ((size_t)blockIdx.x * 256 + threadIdx.x) * 4;
    *(float4*)(p + i) = make_float4(0.f, 0.f, 0.f, 0.f);
}

__global__ __launch_bounds__(256) void bias_init(float* __restrict__ p,
                                                 const float* __restrict__ bias) {
    size_t idx = (size_t)blockIdx.x * 256 + threadIdx.x;   // float4 index
    int col4 = (int)(idx & (DMODEL / 4 - 1));
    *(float4*)(p + idx * 4) = *(const float4*)(bias + col4 * 4);
}

// ======================================================================
// AV: ctx[b,q,h*64+n] += attn[z,q,kslice] @ V[b,kslice,h*64+n]
// CTA 256x64, 4 warps (64x64, M-split); cp.async 3-stage; split-K grid.z
// ======================================================================
#define V_SA 5120   // 256*20 words per stage
#define V_SB 1088   // 16*68 words per stage
#define AV_SPLIT 2
#define AV_KLEN (SEQ / AV_SPLIT)   // 1024

__global__ __launch_bounds__(128) void av_tc(
    const float* __restrict__ attn, const float* __restrict__ V,
    float* __restrict__ ctx)
{
    extern __shared__ float smem[];
    float* sAb = smem;
    float* sBb = smem + 3 * V_SA;

    int tid = threadIdx.x, lane = tid & 31, wid = tid >> 5;
    int grp = lane >> 2, tig = lane & 3;
    int m0 = blockIdx.x * 256;
    int z = blockIdx.y, b = z / NHEADS, h = z % NHEADS;
    int koff = blockIdx.z * AV_KLEN;
    int wm = wid * 64;
    int ar = tid >> 2, ac = (tid & 3) * 4;
    int rv = tid >> 4, cv = (tid & 15) * 4;

    const float* Ab = attn + (size_t)z * APH;
    const float* Vb = V + (size_t)b * SEQ * DMODEL + h * HDIM;

    float acc[4][8][4] = {};

    auto issue = [&](int s, int k0) {
        float* pa = sAb + s * V_SA;
        float* pb = sBb + s * V_SB;
#pragma unroll
        for (int p = 0; p < 8; p++)
            CPA(sptr(pa + (ar + p * 32) * LDM + ac),
                &Ab[(size_t)(m0 + ar + p * 32) * SEQ + koff + k0 + ac]);
#pragma unroll
        for (int p = 0; p < 2; p++)
            CPA(sptr(pb + (rv + p * 8) * LDV + cv),
                &Vb[(size_t)(koff + k0 + rv + p * 8) * DMODEL + cv]);
    };

    const int NIT = AV_KLEN / PBK;  // 64
    issue(0, 0); CPC();
    issue(1, PBK); CPC();

    for (int it = 0; it < NIT; ++it) {
        CPW1();
        __syncthreads();
        int nx = it + 2;
        if (nx < NIT) issue(nx % 3, nx * PBK);
        CPC();
        const float* sa = sAb + (it % 3) * V_SA;
        const float* sb = sBb + (it % 3) * V_SB;
#pragma unroll
        for (int ks = 0; ks < 2; ks++) {
            int kk = ks * 8 + tig;
            unsigned af[4][4], bf8[8][2];
#pragma unroll
            for (int mi = 0; mi < 4; mi++) {
                int mb = wm + mi * 16 + grp;
                af[mi][0] = f2t(sa[mb * LDM + kk]);
                af[mi][1] = f2t(sa[(mb + 8) * LDM + kk]);
                af[mi][2] = f2t(sa[mb * LDM + kk + 4]);
                af[mi][3] = f2t(sa[(mb + 8) * LDM + kk + 4]);
            }
#pragma unroll
            for (int ni = 0; ni < 8; ni++) {
                int nb = ni * 8 + grp;
                bf8[ni][0] = f2t(sb[kk * LDV + nb]);
                bf8[ni][1] = f2t(sb[(kk + 4) * LDV + nb]);
            }
#pragma unroll
            for (int mi = 0; mi < 4; mi++)
#pragma unroll
                for (int ni = 0; ni < 8; ni++) mma8(acc[mi][ni], af[mi], bf8[ni]);
        }
    }

    float* Cb = ctx + (size_t)b * SEQ * DMODEL + h * HDIM;
#pragma unroll
    for (int mi = 0; mi < 4; mi++) {
        int row = m0 + wm + mi * 16 + grp;
#pragma unroll
        for (int ni = 0; ni < 8; ni++) {
            int col = ni * 8 + 2 * tig;
            atomicAdd(&Cb[(size_t)row * DMODEL + col],           acc[mi][ni][0]);
            atomicAdd(&Cb[(size_t)row * DMODEL + col + 1],       acc[mi][ni][1]);
            atomicAdd(&Cb[(size_t)(row + 8) * DMODEL + col],     acc[mi][ni][2]);
            atomicAdd(&Cb[(size_t)(row + 8) * DMODEL + col + 1], acc[mi][ni][3]);
        }
    }
}

extern "C" void kernel_launch(void* const* d_in, const int* in_sizes, int n_in,
                              void* d_out, int out_size) {
    const float* x   = (const float*)d_in[0];
    const float* w_q = (const float*)d_in[1];
    const float* b_q = (const float*)d_in[2];
    const float* w_k = (const float*)d_in[3];
    const float* b_k = (const float*)d_in[4];
    const float* w_v = (const float*)d_in[5];
    const float* b_v = (const float*)d_in[6];
    const float* w_o = (const float*)d_in[7];
    const float* b_o = (const float*)d_in[8];

    float* out  = (float*)d_out;
    float* attn = out + OUT_ELEMS;

    float *q, *k, *v, *ctx;
    cudaGetSymbolAddress((void**)&q,   g_q);
    cudaGetSymbolAddress((void**)&k,   g_k);
    cudaGetSymbolAddress((void**)&v,   g_v);
    cudaGetSymbolAddress((void**)&ctx, g_ctx);

    const int gemmSmem   = (3 * G_SA + 3 * G_SB) * 4;   // 56064 B
    const int scoresSmem = (6 * S_ST) * 4;              // 61440 B
    const int avSmem     = (3 * V_SA + 3 * V_SB) * 4;   // 74496 B
    cudaFuncSetAttribute(gemm3_tc,      cudaFuncAttributeMaxDynamicSharedMemorySize, gemmSmem);
    cudaFuncSetAttribute(gemm_split_tc, cudaFuncAttributeMaxDynamicSharedMemorySize, gemmSmem);
    cudaFuncSetAttribute(scores_tc,     cudaFuncAttributeMaxDynamicSharedMemorySize, scoresSmem);
    cudaFuncSetAttribute(av_tc,         cudaFuncAttributeMaxDynamicSharedMemorySize, avSmem);

    // Fused QKV projections
    GemmArgs qkv;
    qkv.A = x;
    qkv.W[0] = w_q; qkv.W[1] = w_k; qkv.W[2] = w_v;
    qkv.bias[0] = b_q; qkv.bias[1] = b_k; qkv.bias[2] = b_v;
    qkv.C[0] = q; qkv.C[1] = k; qkv.C[2] = v;
    dim3 g1(DMODEL / 128, MTOT / 128, 3);
    gemm3_tc<<<g1, 128, gemmSmem>>>(qkv, MTOT, DMODEL, DMODEL);

    // Scores per (b,h): 2048x2048 = QK^T * scale
    dim3 g2(SEQ / 128, SEQ / 128, BATCH * NHEADS);
    scores_tc<<<g2, 128, scoresSmem>>>(q, k, attn);

    // Softmax over rows (register-resident)
    softmax_rows<<<BATCH * NHEADS * SEQ, 256>>>(attn);

    // ctx = attn @ V, split-K-2 with atomic accumulation
    zero_f4<<<(unsigned)(OUT_ELEMS / (256 * 4)), 256>>>(ctx);
    dim3 g3(SEQ / 256, BATCH * NHEADS, AV_SPLIT);
    av_tc<<<g3, 128, avSmem>>>(attn, v, ctx);

    // out = ctx @ w_o + b_o, split-K-2 (bias pre-seeded)
    bias_init<<<(unsigned)(OUT_ELEMS / (256 * 4)), 256>>>(out, b_o);
    dim3 g4(DMODEL / 128, MTOT / 128, 2);
    gemm_split_tc<<<g4, 128, gemmSmem>>>(ctx, w_o, out, MTOT, DMODEL, DMODEL, DMODEL / 2);
}

// round 12
// speedup vs baseline: 2.0303x; 1.0390x over previous
#include <cuda_runtime.h>
#include <math.h>

// Problem constants
#define BATCH 2
#define SEQ 2048
#define DMODEL 1024
#define NHEADS 16
#define HDIM 64
#define MTOT (BATCH * SEQ)                 // 4096
#define OUT_ELEMS ((size_t)MTOT * DMODEL)  // 4,194,304
#define APH ((size_t)SEQ * SEQ)            // per-head attn elems

// Scratch (allocation-free rule: __device__ globals)
__device__ float g_q[MTOT * DMODEL];
__device__ float g_k[MTOT * DMODEL];
__device__ float g_v[MTOT * DMODEL];
__device__ float g_ctx[MTOT * DMODEL];
// Row-sum partials: [z(32)][ntile(16)][row(2048)]
__device__ float g_rsum[32 * 16 * 2048];

// ---------- tf32 / cp.async helpers ----------
__device__ __forceinline__ unsigned f2t(float x) {
    unsigned u;
    asm("cvt.rna.tf32.f32 %0, %1;" : "=r"(u) : "f"(x));
    return u;
}

__device__ __forceinline__ void mma8(float* d, const unsigned* a, const unsigned* b) {
    asm volatile(
        "mma.sync.aligned.m16n8k8.row.col.f32.tf32.tf32.f32 "
        "{%0,%1,%2,%3}, {%4,%5,%6,%7}, {%8,%9}, {%0,%1,%2,%3};\n"
        : "+f"(d[0]), "+f"(d[1]), "+f"(d[2]), "+f"(d[3])
        : "r"(a[0]), "r"(a[1]), "r"(a[2]), "r"(a[3]), "r"(b[0]), "r"(b[1]));
}

__device__ __forceinline__ unsigned sptr(const void* p) {
    return (unsigned)__cvta_generic_to_shared(p);
}
#define CPA(dst, src) \
    asm volatile("cp.async.cg.shared.global [%0], [%1], 16;\n" :: "r"(dst), "l"(src))
#define CPC() asm volatile("cp.async.commit_group;\n")
#define CPW1() asm volatile("cp.async.wait_group 1;\n" ::: "memory")

#define PBK 16     // K-chunk per smem stage
#define LDM 20     // m-major A-tile row stride (16 + 4 pad), words
#define LDN 132    // k-major B-tile row stride (128 + 4 pad), words
#define LDV 68     // k-major V-tile row stride (64 + 4), words

struct GemmArgs {
    const float* A;
    const float* W[3];
    const float* bias[3];
    float* C[3];
};

// ======================================================================
// GEMM: C[z][M,N] = A[M,K] @ W[z][K,N] + bias[z][N]
// CTA 128x128x16, 4 warps (64x64 each), cp.async 3-stage
// ======================================================================
#define G_SA 2560   // 128*20 words per stage
#define G_SB 2112   // 16*132 words per stage

__global__ __launch_bounds__(128) void gemm3_tc(GemmArgs ga, int M, int N, int K)
{
    extern __shared__ float smem[];
    float* sAb = smem;              // 3 * G_SA
    float* sBb = smem + 3 * G_SA;   // 3 * G_SB

    int tid = threadIdx.x, lane = tid & 31, wid = tid >> 5;
    int grp = lane >> 2, tig = lane & 3;
    int m0 = blockIdx.y * 128, n0 = blockIdx.x * 128;
    int z = blockIdx.z;
    const float* A = ga.A;
    const float* B = ga.W[z];
    const float* bias = ga.bias[z];
    float* C = ga.C[z];

    int wm = (wid >> 1) * 64, wn = (wid & 1) * 64;
    int ar = tid >> 2, ac = (tid & 3) * 4;
    int br = tid >> 5, bc = (tid & 31) * 4;

    float acc[4][8][4] = {};

    auto issue = [&](int s, int k0) {
        float* pa = sAb + s * G_SA;
        float* pb = sBb + s * G_SB;
#pragma unroll
        for (int p = 0; p < 4; p++) {
            CPA(sptr(pa + (ar + p * 32) * LDM + ac),
                &A[(size_t)(m0 + ar + p * 32) * K + k0 + ac]);
            CPA(sptr(pb + (br + p * 4) * LDN + bc),
                &B[(size_t)(k0 + br + p * 4) * N + n0 + bc]);
        }
    };

    int NIT = K / PBK;
    issue(0, 0); CPC();
    issue(1, PBK); CPC();

    for (int it = 0; it < NIT; ++it) {
        CPW1();
        __syncthreads();
        int nx = it + 2;
        if (nx < NIT) issue(nx % 3, nx * PBK);
        CPC();
        const float* sa = sAb + (it % 3) * G_SA;
        const float* sb = sBb + (it % 3) * G_SB;
#pragma unroll
        for (int ks = 0; ks < 2; ks++) {
            int kk = ks * 8 + tig;
            unsigned af[4][4], bf8[8][2];
#pragma unroll
            for (int mi = 0; mi < 4; mi++) {
                int mb = wm + mi * 16 + grp;
                af[mi][0] = f2t(sa[mb * LDM + kk]);
                af[mi][1] = f2t(sa[(mb + 8) * LDM + kk]);
                af[mi][2] = f2t(sa[mb * LDM + kk + 4]);
                af[mi][3] = f2t(sa[(mb + 8) * LDM + kk + 4]);
            }
#pragma unroll
            for (int ni = 0; ni < 8; ni++) {
                int nb = wn + ni * 8 + grp;
                bf8[ni][0] = f2t(sb[kk * LDN + nb]);
                bf8[ni][1] = f2t(sb[(kk + 4) * LDN + nb]);
            }
#pragma unroll
            for (int mi = 0; mi < 4; mi++)
#pragma unroll
                for (int ni = 0; ni < 8; ni++) mma8(acc[mi][ni], af[mi], bf8[ni]);
        }
    }

#pragma unroll
    for (int mi = 0; mi < 4; mi++) {
        int row = m0 + wm + mi * 16 + grp;
#pragma unroll
        for (int ni = 0; ni < 8; ni++) {
            int col = n0 + wn + ni * 8 + 2 * tig;
            float b0 = bias[col], b1 = bias[col + 1];
            C[(size_t)row * N + col]           = acc[mi][ni][0] + b0;
            C[(size_t)row * N + col + 1]       = acc[mi][ni][1] + b1;
            C[(size_t)(row + 8) * N + col]     = acc[mi][ni][2] + b0;
            C[(size_t)(row + 8) * N + col + 1] = acc[mi][ni][3] + b1;
        }
    }
}

// ======================================================================
// Split-K GEMM (accumulate): C[M,N] += A[M,K-slice] @ B[K-slice,N]
// ======================================================================
__global__ __launch_bounds__(128) void gemm_split_tc(
    const float* __restrict__ A, const float* __restrict__ B,
    float* __restrict__ C, int M, int N, int K, int kLen)
{
    extern __shared__ float smem[];
    float* sAb = smem;
    float* sBb = smem + 3 * G_SA;

    int tid = threadIdx.x, lane = tid & 31, wid = tid >> 5;
    int grp = lane >> 2, tig = lane & 3;
    int m0 = blockIdx.y * 128, n0 = blockIdx.x * 128;
    int koff = blockIdx.z * kLen;

    int wm = (wid >> 1) * 64, wn = (wid & 1) * 64;
    int ar = tid >> 2, ac = (tid & 3) * 4;
    int br = tid >> 5, bc = (tid & 31) * 4;

    float acc[4][8][4] = {};

    auto issue = [&](int s, int k0) {
        float* pa = sAb + s * G_SA;
        float* pb = sBb + s * G_SB;
#pragma unroll
        for (int p = 0; p < 4; p++) {
            CPA(sptr(pa + (ar + p * 32) * LDM + ac),
                &A[(size_t)(m0 + ar + p * 32) * K + koff + k0 + ac]);
            CPA(sptr(pb + (br + p * 4) * LDN + bc),
                &B[(size_t)(koff + k0 + br + p * 4) * N + n0 + bc]);
        }
    };

    int NIT = kLen / PBK;
    issue(0, 0); CPC();
    issue(1, PBK); CPC();

    for (int it = 0; it < NIT; ++it) {
        CPW1();
        __syncthreads();
        int nx = it + 2;
        if (nx < NIT) issue(nx % 3, nx * PBK);
        CPC();
        const float* sa = sAb + (it % 3) * G_SA;
        const float* sb = sBb + (it % 3) * G_SB;
#pragma unroll
        for (int ks = 0; ks < 2; ks++) {
            int kk = ks * 8 + tig;
            unsigned af[4][4], bf8[8][2];
#pragma unroll
            for (int mi = 0; mi < 4; mi++) {
                int mb = wm + mi * 16 + grp;
                af[mi][0] = f2t(sa[mb * LDM + kk]);
                af[mi][1] = f2t(sa[(mb + 8) * LDM + kk]);
                af[mi][2] = f2t(sa[mb * LDM + kk + 4]);
                af[mi][3] = f2t(sa[(mb + 8) * LDM + kk + 4]);
            }
#pragma unroll
            for (int ni = 0; ni < 8; ni++) {
                int nb = wn + ni * 8 + grp;
                bf8[ni][0] = f2t(sb[kk * LDN + nb]);
                bf8[ni][1] = f2t(sb[(kk + 4) * LDN + nb]);
            }
#pragma unroll
            for (int mi = 0; mi < 4; mi++)
#pragma unroll
                for (int ni = 0; ni < 8; ni++) mma8(acc[mi][ni], af[mi], bf8[ni]);
        }
    }

#pragma unroll
    for (int mi = 0; mi < 4; mi++) {
        int row = m0 + wm + mi * 16 + grp;
#pragma unroll
        for (int ni = 0; ni < 8; ni++) {
            int col = n0 + wn + ni * 8 + 2 * tig;
            atomicAdd(&C[(size_t)row * N + col],           acc[mi][ni][0]);
            atomicAdd(&C[(size_t)row * N + col + 1],       acc[mi][ni][1]);
            atomicAdd(&C[(size_t)(row + 8) * N + col],     acc[mi][ni][2]);
            atomicAdd(&C[(size_t)(row + 8) * N + col + 1], acc[mi][ni][3]);
        }
    }
}

// ======================================================================
// Scores+exp: attn[z,q,k] = exp((Q_z@K_z^T)*0.125) (UNNORMALIZED) +
// per-row partial sums into g_rsum[z][ntile][row].
// ======================================================================
#define S_ST 2560   // 128*20 words per stage

__global__ __launch_bounds__(128) void scores_exp_tc(
    const float* __restrict__ Q, const float* __restrict__ Km,
    float* __restrict__ attn)
{
    extern __shared__ float smem[];
    float* sAb = smem;
    float* sBb = smem + 3 * S_ST;
    __shared__ float srs[128];

    int tid = threadIdx.x, lane = tid & 31, wid = tid >> 5;
    int grp = lane >> 2, tig = lane & 3;
    int q0 = blockIdx.y * 128, n0 = blockIdx.x * 128;
    int z = blockIdx.z, b = z / NHEADS, h = z % NHEADS;
    int wm = (wid >> 1) * 64, wn = (wid & 1) * 64;
    int ar = tid >> 2, ac = (tid & 3) * 4;

    srs[tid] = 0.f;

    const float* Qb = Q + (size_t)b * SEQ * DMODEL + h * HDIM;
    const float* Kb = Km + (size_t)b * SEQ * DMODEL + h * HDIM;

    float acc[4][8][4] = {};

    auto issue = [&](int s, int k0) {
        float* pa = sAb + s * S_ST;
        float* pb = sBb + s * S_ST;
#pragma unroll
        for (int p = 0; p < 4; p++) {
            CPA(sptr(pa + (ar + p * 32) * LDM + ac),
                &Qb[(size_t)(q0 + ar + p * 32) * DMODEL + k0 + ac]);
            CPA(sptr(pb + (ar + p * 32) * LDM + ac),
                &Kb[(size_t)(n0 + ar + p * 32) * DMODEL + k0 + ac]);
        }
    };

    const int NIT = HDIM / PBK;  // 4
    issue(0, 0); CPC();
    issue(1, PBK); CPC();

    for (int it = 0; it < NIT; ++it) {
        CPW1();
        __syncthreads();
        int nx = it + 2;
        if (nx < NIT) issue(nx % 3, nx * PBK);
        CPC();
        const float* sa = sAb + (it % 3) * S_ST;
        const float* sb = sBb + (it % 3) * S_ST;
#pragma unroll
        for (int ks = 0; ks < 2; ks++) {
            int kk = ks * 8 + tig;
            unsigned af[4][4], bf8[8][2];
#pragma unroll
            for (int mi = 0; mi < 4; mi++) {
                int mb = wm + mi * 16 + grp;
                af[mi][0] = f2t(sa[mb * LDM + kk]);
                af[mi][1] = f2t(sa[(mb + 8) * LDM + kk]);
                af[mi][2] = f2t(sa[mb * LDM + kk + 4]);
                af[mi][3] = f2t(sa[(mb + 8) * LDM + kk + 4]);
            }
#pragma unroll
            for (int ni = 0; ni < 8; ni++) {
                int nb = wn + ni * 8 + grp;
                bf8[ni][0] = f2t(sb[nb * LDM + kk]);
                bf8[ni][1] = f2t(sb[nb * LDM + kk + 4]);
            }
#pragma unroll
            for (int mi = 0; mi < 4; mi++)
#pragma unroll
                for (int ni = 0; ni < 8; ni++) mma8(acc[mi][ni], af[mi], bf8[ni]);
        }
    }

    // Epilogue: e = exp(scale*s); store; reduce row partials
    float* S = attn + (size_t)z * APH;
    const float scale = 0.125f;  // 1/sqrt(64)
#pragma unroll
    for (int mi = 0; mi < 4; mi++) {
        int row = q0 + wm + mi * 16 + grp;
        float r0 = 0.f, r1 = 0.f;
#pragma unroll
        for (int ni = 0; ni < 8; ni++) {
            int col = n0 + wn + ni * 8 + 2 * tig;
            float e0 = __expf(acc[mi][ni][0] * scale);
            float e1 = __expf(acc[mi][ni][1] * scale);
            float e2 = __expf(acc[mi][ni][2] * scale);
            float e3 = __expf(acc[mi][ni][3] * scale);
            S[(size_t)row * SEQ + col]           = e0;
            S[(size_t)row * SEQ + col + 1]       = e1;
            S[(size_t)(row + 8) * SEQ + col]     = e2;
            S[(size_t)(row + 8) * SEQ + col + 1] = e3;
            r0 += e0 + e1;
            r1 += e2 + e3;
        }
        r0 += __shfl_xor_sync(~0u, r0, 1); r0 += __shfl_xor_sync(~0u, r0, 2);
        r1 += __shfl_xor_sync(~0u, r1, 1); r1 += __shfl_xor_sync(~0u, r1, 2);
        if (tig == 0) {
            atomicAdd(&srs[wm + mi * 16 + grp], r0);
            atomicAdd(&srs[wm + mi * 16 + grp + 8], r1);
        }
    }
    __syncthreads();
    g_rsum[((size_t)z * 16 + blockIdx.x) * 2048 + q0 + tid] = srs[tid];
}

// ======================================================================
// Init kernels (streaming)
// ======================================================================
__global__ __launch_bounds__(256) void zero_f4(float* __restrict__ p) {
    size_t i = ((size_t)blockIdx.x * 256 + threadIdx.x) * 4;
    *(float4*)(p + i) = make_float4(0.f, 0.f, 0.f, 0.f);
}

__global__ __launch_bounds__(256) void bias_init(float* __restrict__ p,
                                                 const float* __restrict__ bias) {
    size_t idx = (size_t)blockIdx.x * 256 + threadIdx.x;   // float4 index
    int col4 = (int)(idx & (DMODEL / 4 - 1));
    *(float4*)(p + idx * 4) = *(const float4*)(bias + col4 * 4);
}

// ======================================================================
// AV + normalize: reads exp-attn, writes normalized attn back (streamed),
// ctx += (exp-attn @ V) * inv_row   (normalization in epilogue).
// CTA 256x64, 4 warps (64x64, M-split); cp.async 3-stage; split-K grid.z
// ======================================================================
#define V_SA 5120   // 256*20 words per stage
#define V_SB 1088   // 16*68 words per stage
#define AV_SPLIT 2
#define AV_KLEN (SEQ / AV_SPLIT)   // 1024

__global__ __launch_bounds__(128, 3) void av_tc(
    float* __restrict__ attn, const float* __restrict__ V,
    float* __restrict__ ctx)
{
    extern __shared__ float smem[];
    float* sAb = smem;                       // 3 * V_SA
    float* sBb = smem + 3 * V_SA;            // 3 * V_SB
    float* sinv = smem + 3 * V_SA + 3 * V_SB;  // 256 row inverses

    int tid = threadIdx.x, lane = tid & 31, wid = tid >> 5;
    int grp = lane >> 2, tig = lane & 3;
    int m0 = blockIdx.x * 256;
    int z = blockIdx.y, b = z / NHEADS, h = z % NHEADS;
    int koff = blockIdx.z * AV_KLEN;
    int wm = wid * 64;
    int ar = tid >> 2, ac = (tid & 3) * 4;
    int rv = tid >> 4, cv = (tid & 15) * 4;

    float* Ab = attn + (size_t)z * APH;
    const float* Vb = V + (size_t)b * SEQ * DMODEL + h * HDIM;

    // Row inverse sums from the 16 scores partials
    {
        float s0 = 0.f, s1 = 0.f;
        const float* rp = &g_rsum[(size_t)z * 16 * 2048 + m0];
#pragma unroll
        for (int t = 0; t < 16; t++) {
            s0 += rp[t * 2048 + tid];
            s1 += rp[t * 2048 + tid + 128];
        }
        sinv[tid] = 1.f / s0;
        sinv[tid + 128] = 1.f / s1;
    }

    float acc[4][8][4] = {};

    auto issue = [&](int s, int k0) {
        float* pa = sAb + s * V_SA;
        float* pb = sBb + s * V_SB;
#pragma unroll
        for (int p = 0; p < 8; p++)
            CPA(sptr(pa + (ar + p * 32) * LDM + ac),
                &Ab[(size_t)(m0 + ar + p * 32) * SEQ + koff + k0 + ac]);
#pragma unroll
        for (int p = 0; p < 2; p++)
            CPA(sptr(pb + (rv + p * 8) * LDV + cv),
                &Vb[(size_t)(koff + k0 + rv + p * 8) * DMODEL + cv]);
    };

    const int NIT = AV_KLEN / PBK;  // 64
    issue(0, 0); CPC();
    issue(1, PBK); CPC();
    __syncthreads();   // sinv visible to all threads

    // Per-thread row inverses for the write-back rows (loop-invariant)
    float winv[8];
#pragma unroll
    for (int p = 0; p < 8; p++) winv[p] = sinv[ar + p * 32];

    for (int it = 0; it < NIT; ++it) {
        CPW1();
        __syncthreads();
        int nx = it + 2;
        if (nx < NIT) issue(nx % 3, nx * PBK);
        CPC();
        const float* sa = sAb + (it % 3) * V_SA;
        const float* sb = sBb + (it % 3) * V_SB;
#pragma unroll
        for (int ks = 0; ks < 2; ks++) {
            int kk = ks * 8 + tig;
            unsigned af[4][4], bf8[8][2];
#pragma unroll
            for (int mi = 0; mi < 4; mi++) {
                int mb = wm + mi * 16 + grp;
                af[mi][0] = f2t(sa[mb * LDM + kk]);
                af[mi][1] = f2t(sa[(mb + 8) * LDM + kk]);
                af[mi][2] = f2t(sa[mb * LDM + kk + 4]);
                af[mi][3] = f2t(sa[(mb + 8) * LDM + kk + 4]);
            }
#pragma unroll
            for (int ni = 0; ni < 8; ni++) {
                int nb = ni * 8 + grp;
                bf8[ni][0] = f2t(sb[kk * LDV + nb]);
                bf8[ni][1] = f2t(sb[(kk + 4) * LDV + nb]);
            }
#pragma unroll
            for (int mi = 0; mi < 4; mi++)
#pragma unroll
                for (int ni = 0; ni < 8; ni++) mma8(acc[mi][ni], af[mi], bf8[ni]);
        }
        // Write back normalized attn for this tile (each thread stores what
        // it loaded: rows ar+p*32, cols koff + it*PBK + ac .. +3)
        {
            int kg = koff + it * PBK + ac;
#pragma unroll
            for (int p = 0; p < 8; p++) {
                const float* src = sa + (ar + p * 32) * LDM + ac;
                float4 t;
                t.x = src[0] * winv[p];
                t.y = src[1] * winv[p];
                t.z = src[2] * winv[p];
                t.w = src[3] * winv[p];
                *(float4*)&Ab[(size_t)(m0 + ar + p * 32) * SEQ + kg] = t;
            }
        }
    }

    // Epilogue: normalize ctx contributions by row inverses
    float* Cb = ctx + (size_t)b * SEQ * DMODEL + h * HDIM;
#pragma unroll
    for (int mi = 0; mi < 4; mi++) {
        int mb = wm + mi * 16 + grp;
        int row = m0 + mb;
        float i0 = sinv[mb], i1 = sinv[mb + 8];
#pragma unroll
        for (int ni = 0; ni < 8; ni++) {
            int col = ni * 8 + 2 * tig;
            atomicAdd(&Cb[(size_t)row * DMODEL + col],           acc[mi][ni][0] * i0);
            atomicAdd(&Cb[(size_t)row * DMODEL + col + 1],       acc[mi][ni][1] * i0);
            atomicAdd(&Cb[(size_t)(row + 8) * DMODEL + col],     acc[mi][ni][2] * i1);
            atomicAdd(&Cb[(size_t)(row + 8) * DMODEL + col + 1], acc[mi][ni][3] * i1);
        }
    }
}

extern "C" void kernel_launch(void* const* d_in, const int* in_sizes, int n_in,
                              void* d_out, int out_size) {
    const float* x   = (const float*)d_in[0];
    const float* w_q = (const float*)d_in[1];
    const float* b_q = (const float*)d_in[2];
    const float* w_k = (const float*)d_in[3];
    const float* b_k = (const float*)d_in[4];
    const float* w_v = (const float*)d_in[5];
    const float* b_v = (const float*)d_in[6];
    const float* w_o = (const float*)d_in[7];
    const float* b_o = (const float*)d_in[8];

    float* out  = (float*)d_out;
    float* attn = out + OUT_ELEMS;

    float *q, *k, *v, *ctx;
    cudaGetSymbolAddress((void**)&q,   g_q);
    cudaGetSymbolAddress((void**)&k,   g_k);
    cudaGetSymbolAddress((void**)&v,   g_v);
    cudaGetSymbolAddress((void**)&ctx, g_ctx);

    const int gemmSmem   = (3 * G_SA + 3 * G_SB) * 4;          // 56064 B
    const int scoresSmem = (6 * S_ST) * 4;                     // 61440 B
    const int avSmem     = (3 * V_SA + 3 * V_SB + 256) * 4;    // 75520 B
    cudaFuncSetAttribute(gemm3_tc,      cudaFuncAttributeMaxDynamicSharedMemorySize, gemmSmem);
    cudaFuncSetAttribute(gemm_split_tc, cudaFuncAttributeMaxDynamicSharedMemorySize, gemmSmem);
    cudaFuncSetAttribute(scores_exp_tc, cudaFuncAttributeMaxDynamicSharedMemorySize, scoresSmem);
    cudaFuncSetAttribute(av_tc,         cudaFuncAttributeMaxDynamicSharedMemorySize, avSmem);

    // Fused QKV projections
    GemmArgs qkv;
    qkv.A = x;
    qkv.W[0] = w_q; qkv.W[1] = w_k; qkv.W[2] = w_v;
    qkv.bias[0] = b_q; qkv.bias[1] = b_k; qkv.bias[2] = b_v;
    qkv.C[0] = q; qkv.C[1] = k; qkv.C[2] = v;
    dim3 g1(DMODEL / 128, MTOT / 128, 3);
    gemm3_tc<<<g1, 128, gemmSmem>>>(qkv, MTOT, DMODEL, DMODEL);

    // Scores + exp + row-sum partials (no separate softmax kernel)
    dim3 g2(SEQ / 128, SEQ / 128, BATCH * NHEADS);
    scores_exp_tc<<<g2, 128, scoresSmem>>>(q, k, attn);

    // ctx = softmax @ V (normalization fused); normalized attn written back
    zero_f4<<<(unsigned)(OUT_ELEMS / (256 * 4)), 256>>>(ctx);
    dim3 g3(SEQ / 256, BATCH * NHEADS, AV_SPLIT);
    av_tc<<<g3, 128, avSmem>>>(attn, v, ctx);

    // out = ctx @ w_o + b_o, split-K-2 (bias pre-seeded)
    bias_init<<<(unsigned)(OUT_ELEMS / (256 * 4)), 256>>>(out, b_o);
    dim3 g4(DMODEL / 128, MTOT / 128, 2);
    gemm_split_tc<<<g4, 128, gemmSmem>>>(ctx, w_o, out, MTOT, DMODEL, DMODEL, DMODEL / 2);
}

// round 13
// speedup vs baseline: 2.0428x; 1.0062x over previous
#include <cuda_runtime.h>
#include <math.h>

// Problem constants
#define BATCH 2
#define SEQ 2048
#define DMODEL 1024
#define NHEADS 16
#define HDIM 64
#define MTOT (BATCH * SEQ)                 // 4096
#define OUT_ELEMS ((size_t)MTOT * DMODEL)  // 4,194,304
#define APH ((size_t)SEQ * SEQ)            // per-head attn elems

// Scratch (allocation-free rule: __device__ globals)
__device__ float g_q[MTOT * DMODEL];
__device__ float g_k[MTOT * DMODEL];
__device__ float g_v[MTOT * DMODEL];
__device__ float g_ctx[MTOT * DMODEL];
// Row-sum partials: [z(32)][ntile(16)][row(2048)]
__device__ float g_rsum[32 * 16 * 2048];

// ---------- tf32 / cp.async helpers ----------
__device__ __forceinline__ unsigned f2t(float x) {
    unsigned u;
    asm("cvt.rna.tf32.f32 %0, %1;" : "=r"(u) : "f"(x));
    return u;
}

__device__ __forceinline__ void mma8(float* d, const unsigned* a, const unsigned* b) {
    asm volatile(
        "mma.sync.aligned.m16n8k8.row.col.f32.tf32.tf32.f32 "
        "{%0,%1,%2,%3}, {%4,%5,%6,%7}, {%8,%9}, {%0,%1,%2,%3};\n"
        : "+f"(d[0]), "+f"(d[1]), "+f"(d[2]), "+f"(d[3])
        : "r"(a[0]), "r"(a[1]), "r"(a[2]), "r"(a[3]), "r"(b[0]), "r"(b[1]));
}

__device__ __forceinline__ unsigned sptr(const void* p) {
    return (unsigned)__cvta_generic_to_shared(p);
}
#define CPA(dst, src) \
    asm volatile("cp.async.cg.shared.global [%0], [%1], 16;\n" :: "r"(dst), "l"(src))
#define CPC() asm volatile("cp.async.commit_group;\n")
#define CPW1() asm volatile("cp.async.wait_group 1;\n" ::: "memory")

#define PBK 16     // K-chunk per smem stage
#define LDM 20     // m-major A-tile row stride (16 + 4 pad), words
#define LDN 132    // k-major B-tile row stride (128 + 4 pad), words
#define LDV 68     // k-major V-tile row stride (64 + 4), words

struct GemmArgs {
    const float* A;
    const float* W[3];
    const float* bias[3];
    float* C[3];
};

// ======================================================================
// GEMM: C[z][M,N] = A[M,K] @ W[z][K,N] + bias[z][N]
// CTA 128x128x16, 4 warps (64x64 each), cp.async 3-stage
// ======================================================================
#define G_SA 2560   // 128*20 words per stage
#define G_SB 2112   // 16*132 words per stage

__global__ __launch_bounds__(128) void gemm3_tc(GemmArgs ga, int M, int N, int K)
{
    extern __shared__ float smem[];
    float* sAb = smem;              // 3 * G_SA
    float* sBb = smem + 3 * G_SA;   // 3 * G_SB

    int tid = threadIdx.x, lane = tid & 31, wid = tid >> 5;
    int grp = lane >> 2, tig = lane & 3;
    int m0 = blockIdx.y * 128, n0 = blockIdx.x * 128;
    int z = blockIdx.z;
    const float* A = ga.A;
    const float* B = ga.W[z];
    const float* bias = ga.bias[z];
    float* C = ga.C[z];

    int wm = (wid >> 1) * 64, wn = (wid & 1) * 64;
    int ar = tid >> 2, ac = (tid & 3) * 4;
    int br = tid >> 5, bc = (tid & 31) * 4;

    float acc[4][8][4] = {};

    auto issue = [&](int s, int k0) {
        float* pa = sAb + s * G_SA;
        float* pb = sBb + s * G_SB;
#pragma unroll
        for (int p = 0; p < 4; p++) {
            CPA(sptr(pa + (ar + p * 32) * LDM + ac),
                &A[(size_t)(m0 + ar + p * 32) * K + k0 + ac]);
            CPA(sptr(pb + (br + p * 4) * LDN + bc),
                &B[(size_t)(k0 + br + p * 4) * N + n0 + bc]);
        }
    };

    int NIT = K / PBK;
    issue(0, 0); CPC();
    issue(1, PBK); CPC();

    for (int it = 0; it < NIT; ++it) {
        CPW1();
        __syncthreads();
        int nx = it + 2;
        if (nx < NIT) issue(nx % 3, nx * PBK);
        CPC();
        const float* sa = sAb + (it % 3) * G_SA;
        const float* sb = sBb + (it % 3) * G_SB;
#pragma unroll
        for (int ks = 0; ks < 2; ks++) {
            int kk = ks * 8 + tig;
            unsigned af[4][4], bf8[8][2];
#pragma unroll
            for (int mi = 0; mi < 4; mi++) {
                int mb = wm + mi * 16 + grp;
                af[mi][0] = f2t(sa[mb * LDM + kk]);
                af[mi][1] = f2t(sa[(mb + 8) * LDM + kk]);
                af[mi][2] = f2t(sa[mb * LDM + kk + 4]);
                af[mi][3] = f2t(sa[(mb + 8) * LDM + kk + 4]);
            }
#pragma unroll
            for (int ni = 0; ni < 8; ni++) {
                int nb = wn + ni * 8 + grp;
                bf8[ni][0] = f2t(sb[kk * LDN + nb]);
                bf8[ni][1] = f2t(sb[(kk + 4) * LDN + nb]);
            }
#pragma unroll
            for (int mi = 0; mi < 4; mi++)
#pragma unroll
                for (int ni = 0; ni < 8; ni++) mma8(acc[mi][ni], af[mi], bf8[ni]);
        }
    }

#pragma unroll
    for (int mi = 0; mi < 4; mi++) {
        int row = m0 + wm + mi * 16 + grp;
#pragma unroll
        for (int ni = 0; ni < 8; ni++) {
            int col = n0 + wn + ni * 8 + 2 * tig;
            float b0 = bias[col], b1 = bias[col + 1];
            C[(size_t)row * N + col]           = acc[mi][ni][0] + b0;
            C[(size_t)row * N + col + 1]       = acc[mi][ni][1] + b1;
            C[(size_t)(row + 8) * N + col]     = acc[mi][ni][2] + b0;
            C[(size_t)(row + 8) * N + col + 1] = acc[mi][ni][3] + b1;
        }
    }
}

// ======================================================================
// Split-K GEMM (accumulate): C[M,N] += A[M,K-slice] @ B[K-slice,N]
// ======================================================================
__global__ __launch_bounds__(128) void gemm_split_tc(
    const float* __restrict__ A, const float* __restrict__ B,
    float* __restrict__ C, int M, int N, int K, int kLen)
{
    extern __shared__ float smem[];
    float* sAb = smem;
    float* sBb = smem + 3 * G_SA;

    int tid = threadIdx.x, lane = tid & 31, wid = tid >> 5;
    int grp = lane >> 2, tig = lane & 3;
    int m0 = blockIdx.y * 128, n0 = blockIdx.x * 128;
    int koff = blockIdx.z * kLen;

    int wm = (wid >> 1) * 64, wn = (wid & 1) * 64;
    int ar = tid >> 2, ac = (tid & 3) * 4;
    int br = tid >> 5, bc = (tid & 31) * 4;

    float acc[4][8][4] = {};

    auto issue = [&](int s, int k0) {
        float* pa = sAb + s * G_SA;
        float* pb = sBb + s * G_SB;
#pragma unroll
        for (int p = 0; p < 4; p++) {
            CPA(sptr(pa + (ar + p * 32) * LDM + ac),
                &A[(size_t)(m0 + ar + p * 32) * K + koff + k0 + ac]);
            CPA(sptr(pb + (br + p * 4) * LDN + bc),
                &B[(size_t)(koff + k0 + br + p * 4) * N + n0 + bc]);
        }
    };

    int NIT = kLen / PBK;
    issue(0, 0); CPC();
    issue(1, PBK); CPC();

    for (int it = 0; it < NIT; ++it) {
        CPW1();
        __syncthreads();
        int nx = it + 2;
        if (nx < NIT) issue(nx % 3, nx * PBK);
        CPC();
        const float* sa = sAb + (it % 3) * G_SA;
        const float* sb = sBb + (it % 3) * G_SB;
#pragma unroll
        for (int ks = 0; ks < 2; ks++) {
            int kk = ks * 8 + tig;
            unsigned af[4][4], bf8[8][2];
#pragma unroll
            for (int mi = 0; mi < 4; mi++) {
                int mb = wm + mi * 16 + grp;
                af[mi][0] = f2t(sa[mb * LDM + kk]);
                af[mi][1] = f2t(sa[(mb + 8) * LDM + kk]);
                af[mi][2] = f2t(sa[mb * LDM + kk + 4]);
                af[mi][3] = f2t(sa[(mb + 8) * LDM + kk + 4]);
            }
#pragma unroll
            for (int ni = 0; ni < 8; ni++) {
                int nb = wn + ni * 8 + grp;
                bf8[ni][0] = f2t(sb[kk * LDN + nb]);
                bf8[ni][1] = f2t(sb[(kk + 4) * LDN + nb]);
            }
#pragma unroll
            for (int mi = 0; mi < 4; mi++)
#pragma unroll
                for (int ni = 0; ni < 8; ni++) mma8(acc[mi][ni], af[mi], bf8[ni]);
        }
    }

#pragma unroll
    for (int mi = 0; mi < 4; mi++) {
        int row = m0 + wm + mi * 16 + grp;
#pragma unroll
        for (int ni = 0; ni < 8; ni++) {
            int col = n0 + wn + ni * 8 + 2 * tig;
            atomicAdd(&C[(size_t)row * N + col],           acc[mi][ni][0]);
            atomicAdd(&C[(size_t)row * N + col + 1],       acc[mi][ni][1]);
            atomicAdd(&C[(size_t)(row + 8) * N + col],     acc[mi][ni][2]);
            atomicAdd(&C[(size_t)(row + 8) * N + col + 1], acc[mi][ni][3]);
        }
    }
}

// ======================================================================
// Scores+exp: attn[z,q,k] = exp((Q_z@K_z^T)*0.125) (UNNORMALIZED) +
// per-row partial sums into g_rsum[z][ntile][row].
// ======================================================================
#define S_ST 2560   // 128*20 words per stage

__global__ __launch_bounds__(128) void scores_exp_tc(
    const float* __restrict__ Q, const float* __restrict__ Km,
    float* __restrict__ attn)
{
    extern __shared__ float smem[];
    float* sAb = smem;
    float* sBb = smem + 3 * S_ST;
    __shared__ float srs[128];

    int tid = threadIdx.x, lane = tid & 31, wid = tid >> 5;
    int grp = lane >> 2, tig = lane & 3;
    int q0 = blockIdx.y * 128, n0 = blockIdx.x * 128;
    int z = blockIdx.z, b = z / NHEADS, h = z % NHEADS;
    int wm = (wid >> 1) * 64, wn = (wid & 1) * 64;
    int ar = tid >> 2, ac = (tid & 3) * 4;

    srs[tid] = 0.f;

    const float* Qb = Q + (size_t)b * SEQ * DMODEL + h * HDIM;
    const float* Kb = Km + (size_t)b * SEQ * DMODEL + h * HDIM;

    float acc[4][8][4] = {};

    auto issue = [&](int s, int k0) {
        float* pa = sAb + s * S_ST;
        float* pb = sBb + s * S_ST;
#pragma unroll
        for (int p = 0; p < 4; p++) {
            CPA(sptr(pa + (ar + p * 32) * LDM + ac),
                &Qb[(size_t)(q0 + ar + p * 32) * DMODEL + k0 + ac]);
            CPA(sptr(pb + (ar + p * 32) * LDM + ac),
                &Kb[(size_t)(n0 + ar + p * 32) * DMODEL + k0 + ac]);
        }
    };

    const int NIT = HDIM / PBK;  // 4
    issue(0, 0); CPC();
    issue(1, PBK); CPC();

    for (int it = 0; it < NIT; ++it) {
        CPW1();
        __syncthreads();
        int nx = it + 2;
        if (nx < NIT) issue(nx % 3, nx * PBK);
        CPC();
        const float* sa = sAb + (it % 3) * S_ST;
        const float* sb = sBb + (it % 3) * S_ST;
#pragma unroll
        for (int ks = 0; ks < 2; ks++) {
            int kk = ks * 8 + tig;
            unsigned af[4][4], bf8[8][2];
#pragma unroll
            for (int mi = 0; mi < 4; mi++) {
                int mb = wm + mi * 16 + grp;
                af[mi][0] = f2t(sa[mb * LDM + kk]);
                af[mi][1] = f2t(sa[(mb + 8) * LDM + kk]);
                af[mi][2] = f2t(sa[mb * LDM + kk + 4]);
                af[mi][3] = f2t(sa[(mb + 8) * LDM + kk + 4]);
            }
#pragma unroll
            for (int ni = 0; ni < 8; ni++) {
                int nb = wn + ni * 8 + grp;
                bf8[ni][0] = f2t(sb[nb * LDM + kk]);
                bf8[ni][1] = f2t(sb[nb * LDM + kk + 4]);
            }
#pragma unroll
            for (int mi = 0; mi < 4; mi++)
#pragma unroll
                for (int ni = 0; ni < 8; ni++) mma8(acc[mi][ni], af[mi], bf8[ni]);
        }
    }

    // Epilogue: e = exp(scale*s); store; reduce row partials
    float* S = attn + (size_t)z * APH;
    const float scale = 0.125f;  // 1/sqrt(64)
#pragma unroll
    for (int mi = 0; mi < 4; mi++) {
        int row = q0 + wm + mi * 16 + grp;
        float r0 = 0.f, r1 = 0.f;
#pragma unroll
        for (int ni = 0; ni < 8; ni++) {
            int col = n0 + wn + ni * 8 + 2 * tig;
            float e0 = __expf(acc[mi][ni][0] * scale);
            float e1 = __expf(acc[mi][ni][1] * scale);
            float e2 = __expf(acc[mi][ni][2] * scale);
            float e3 = __expf(acc[mi][ni][3] * scale);
            S[(size_t)row * SEQ + col]           = e0;
            S[(size_t)row * SEQ + col + 1]       = e1;
            S[(size_t)(row + 8) * SEQ + col]     = e2;
            S[(size_t)(row + 8) * SEQ + col + 1] = e3;
            r0 += e0 + e1;
            r1 += e2 + e3;
        }
        r0 += __shfl_xor_sync(~0u, r0, 1); r0 += __shfl_xor_sync(~0u, r0, 2);
        r1 += __shfl_xor_sync(~0u, r1, 1); r1 += __shfl_xor_sync(~0u, r1, 2);
        if (tig == 0) {
            atomicAdd(&srs[wm + mi * 16 + grp], r0);
            atomicAdd(&srs[wm + mi * 16 + grp + 8], r1);
        }
    }
    __syncthreads();
    g_rsum[((size_t)z * 16 + blockIdx.x) * 2048 + q0 + tid] = srs[tid];
}

// ======================================================================
// Init kernels (streaming)
// ======================================================================
__global__ __launch_bounds__(256) void zero_f4(float* __restrict__ p) {
    size_t i = ((size_t)blockIdx.x * 256 + threadIdx.x) * 4;
    *(float4*)(p + i) = make_float4(0.f, 0.f, 0.f, 0.f);
}

__global__ __launch_bounds__(256) void bias_init(float* __restrict__ p,
                                                 const float* __restrict__ bias) {
    size_t idx = (size_t)blockIdx.x * 256 + threadIdx.x;   // float4 index
    int col4 = (int)(idx & (DMODEL / 4 - 1));
    *(float4*)(p + idx * 4) = *(const float4*)(bias + col4 * 4);
}

// ======================================================================
// AV + normalize: reads exp-attn, writes normalized attn back (streamed),
// ctx += (exp-attn @ V) * inv_row   (normalization in epilogue).
// CTA 256x64, 8 warps (32x64 each, M-split); cp.async 3-stage; split-K
// ======================================================================
#define V_SA 5120   // 256*20 words per stage
#define V_SB 1088   // 16*68 words per stage
#define AV_SPLIT 2
#define AV_KLEN (SEQ / AV_SPLIT)   // 1024

__global__ __launch_bounds__(256, 2) void av_tc(
    float* __restrict__ attn, const float* __restrict__ V,
    float* __restrict__ ctx)
{
    extern __shared__ float smem[];
    float* sAb = smem;                         // 3 * V_SA
    float* sBb = smem + 3 * V_SA;              // 3 * V_SB
    float* sinv = smem + 3 * V_SA + 3 * V_SB;  // 256 row inverses

    int tid = threadIdx.x, lane = tid & 31, wid = tid >> 5;
    int grp = lane >> 2, tig = lane & 3;
    int m0 = blockIdx.x * 256;
    int z = blockIdx.y, b = z / NHEADS, h = z % NHEADS;
    int koff = blockIdx.z * AV_KLEN;
    int wm = wid * 32;                       // 8 warps split M, all share N=64
    int ar = tid >> 2, ac = (tid & 3) * 4;   // A: rows ar+p*64 (p<4), k-cols ac
    int rv = tid >> 4, cv = (tid & 15) * 4;  // V: k-row rv, n-cols cv

    float* Ab = attn + (size_t)z * APH;
    const float* Vb = V + (size_t)b * SEQ * DMODEL + h * HDIM;

    // Row inverse sums from the 16 scores partials
    {
        float s0 = 0.f;
        const float* rp = &g_rsum[(size_t)z * 16 * 2048 + m0];
#pragma unroll
        for (int t = 0; t < 16; t++) s0 += rp[t * 2048 + tid];
        sinv[tid] = 1.f / s0;
    }

    float acc[2][8][4] = {};

    auto issue = [&](int s, int k0) {
        float* pa = sAb + s * V_SA;
        float* pb = sBb + s * V_SB;
#pragma unroll
        for (int p = 0; p < 4; p++)
            CPA(sptr(pa + (ar + p * 64) * LDM + ac),
                &Ab[(size_t)(m0 + ar + p * 64) * SEQ + koff + k0 + ac]);
        CPA(sptr(pb + rv * LDV + cv),
            &Vb[(size_t)(koff + k0 + rv) * DMODEL + cv]);
    };

    const int NIT = AV_KLEN / PBK;  // 64
    issue(0, 0); CPC();
    issue(1, PBK); CPC();
    __syncthreads();   // sinv visible to all threads

    // Per-thread row inverses for the write-back rows (loop-invariant)
    float winv[4];
#pragma unroll
    for (int p = 0; p < 4; p++) winv[p] = sinv[ar + p * 64];

    for (int it = 0; it < NIT; ++it) {
        CPW1();
        __syncthreads();
        int nx = it + 2;
        if (nx < NIT) issue(nx % 3, nx * PBK);
        CPC();
        const float* sa = sAb + (it % 3) * V_SA;
        const float* sb = sBb + (it % 3) * V_SB;
#pragma unroll
        for (int ks = 0; ks < 2; ks++) {
            int kk = ks * 8 + tig;
            unsigned af[2][4], bf8[8][2];
#pragma unroll
            for (int mi = 0; mi < 2; mi++) {
                int mb = wm + mi * 16 + grp;
                af[mi][0] = f2t(sa[mb * LDM + kk]);
                af[mi][1] = f2t(sa[(mb + 8) * LDM + kk]);
                af[mi][2] = f2t(sa[mb * LDM + kk + 4]);
                af[mi][3] = f2t(sa[(mb + 8) * LDM + kk + 4]);
            }
#pragma unroll
            for (int ni = 0; ni < 8; ni++) {
                int nb = ni * 8 + grp;
                bf8[ni][0] = f2t(sb[kk * LDV + nb]);
                bf8[ni][1] = f2t(sb[(kk + 4) * LDV + nb]);
            }
#pragma unroll
            for (int mi = 0; mi < 2; mi++)
#pragma unroll
                for (int ni = 0; ni < 8; ni++) mma8(acc[mi][ni], af[mi], bf8[ni]);
        }
        // Write back normalized attn for this tile (each thread stores what
        // it loaded: rows ar+p*64, cols koff + it*PBK + ac .. +3)
        {
            int kg = koff + it * PBK + ac;
#pragma unroll
            for (int p = 0; p < 4; p++) {
                const float* src = sa + (ar + p * 64) * LDM + ac;
                float4 t;
                t.x = src[0] * winv[p];
                t.y = src[1] * winv[p];
                t.z = src[2] * winv[p];
                t.w = src[3] * winv[p];
                *(float4*)&Ab[(size_t)(m0 + ar + p * 64) * SEQ + kg] = t;
            }
        }
    }

    // Epilogue: normalize ctx contributions by row inverses
    float* Cb = ctx + (size_t)b * SEQ * DMODEL + h * HDIM;
#pragma unroll
    for (int mi = 0; mi < 2; mi++) {
        int mb = wm + mi * 16 + grp;
        int row = m0 + mb;
        float i0 = sinv[mb], i1 = sinv[mb + 8];
#pragma unroll
        for (int ni = 0; ni < 8; ni++) {
            int col = ni * 8 + 2 * tig;
            atomicAdd(&Cb[(size_t)row * DMODEL + col],           acc[mi][ni][0] * i0);
            atomicAdd(&Cb[(size_t)row * DMODEL + col + 1],       acc[mi][ni][1] * i0);
            atomicAdd(&Cb[(size_t)(row + 8) * DMODEL + col],     acc[mi][ni][2] * i1);
            atomicAdd(&Cb[(size_t)(row + 8) * DMODEL + col + 1], acc[mi][ni][3] * i1);
        }
    }
}

extern "C" void kernel_launch(void* const* d_in, const int* in_sizes, int n_in,
                              void* d_out, int out_size) {
    const float* x   = (const float*)d_in[0];
    const float* w_q = (const float*)d_in[1];
    const float* b_q = (const float*)d_in[2];
    const float* w_k = (const float*)d_in[3];
    const float* b_k = (const float*)d_in[4];
    const float* w_v = (const float*)d_in[5];
    const float* b_v = (const float*)d_in[6];
    const float* w_o = (const float*)d_in[7];
    const float* b_o = (const float*)d_in[8];

    float* out  = (float*)d_out;
    float* attn = out + OUT_ELEMS;

    float *q, *k, *v, *ctx;
    cudaGetSymbolAddress((void**)&q,   g_q);
    cudaGetSymbolAddress((void**)&k,   g_k);
    cudaGetSymbolAddress((void**)&v,   g_v);
    cudaGetSymbolAddress((void**)&ctx, g_ctx);

    const int gemmSmem   = (3 * G_SA + 3 * G_SB) * 4;          // 56064 B
    const int scoresSmem = (6 * S_ST) * 4;                     // 61440 B
    const int avSmem     = (3 * V_SA + 3 * V_SB + 256) * 4;    // 75520 B
    cudaFuncSetAttribute(gemm3_tc,      cudaFuncAttributeMaxDynamicSharedMemorySize, gemmSmem);
    cudaFuncSetAttribute(gemm_split_tc, cudaFuncAttributeMaxDynamicSharedMemorySize, gemmSmem);
    cudaFuncSetAttribute(scores_exp_tc, cudaFuncAttributeMaxDynamicSharedMemorySize, scoresSmem);
    cudaFuncSetAttribute(av_tc,         cudaFuncAttributeMaxDynamicSharedMemorySize, avSmem);

    // Fused QKV projections
    GemmArgs qkv;
    qkv.A = x;
    qkv.W[0] = w_q; qkv.W[1] = w_k; qkv.W[2] = w_v;
    qkv.bias[0] = b_q; qkv.bias[1] = b_k; qkv.bias[2] = b_v;
    qkv.C[0] = q; qkv.C[1] = k; qkv.C[2] = v;
    dim3 g1(DMODEL / 128, MTOT / 128, 3);
    gemm3_tc<<<g1, 128, gemmSmem>>>(qkv, MTOT, DMODEL, DMODEL);

    // Scores + exp + row-sum partials (no separate softmax kernel)
    dim3 g2(SEQ / 128, SEQ / 128, BATCH * NHEADS);
    scores_exp_tc<<<g2, 128, scoresSmem>>>(q, k, attn);

    // ctx = softmax @ V (normalization fused); normalized attn written back
    zero_f4<<<(unsigned)(OUT_ELEMS / (256 * 4)), 256>>>(ctx);
    dim3 g3(SEQ / 256, BATCH * NHEADS, AV_SPLIT);
    av_tc<<<g3, 256, avSmem>>>(attn, v, ctx);

    // out = ctx @ w_o + b_o, split-K-2 (bias pre-seeded)
    bias_init<<<(unsigned)(OUT_ELEMS / (256 * 4)), 256>>>(out, b_o);
    dim3 g4(DMODEL / 128, MTOT / 128, 2);
    gemm_split_tc<<<g4, 128, gemmSmem>>>(ctx, w_o, out, MTOT, DMODEL, DMODEL, DMODEL / 2);
}

// round 14
// speedup vs baseline: 2.0773x; 1.0169x over previous
#include <cuda_runtime.h>
#include <math.h>

// Problem constants
#define BATCH 2
#define SEQ 2048
#define DMODEL 1024
#define NHEADS 16
#define HDIM 64
#define MTOT (BATCH * SEQ)                 // 4096
#define OUT_ELEMS ((size_t)MTOT * DMODEL)  // 4,194,304
#define APH ((size_t)SEQ * SEQ)            // per-head attn elems

// Scratch (allocation-free rule: __device__ globals)
__device__ float g_q[MTOT * DMODEL];
__device__ float g_k[MTOT * DMODEL];
__device__ float g_v[MTOT * DMODEL];
__device__ float g_ctx[MTOT * DMODEL];
// Row-sum partials: [z(32)][ntile(16)][row(2048)]
__device__ float g_rsum[32 * 16 * 2048];

// ---------- tf32 / cp.async helpers ----------
__device__ __forceinline__ unsigned f2t(float x) {
    unsigned u;
    asm("cvt.rna.tf32.f32 %0, %1;" : "=r"(u) : "f"(x));
    return u;
}

__device__ __forceinline__ void mma8(float* d, const unsigned* a, const unsigned* b) {
    asm volatile(
        "mma.sync.aligned.m16n8k8.row.col.f32.tf32.tf32.f32 "
        "{%0,%1,%2,%3}, {%4,%5,%6,%7}, {%8,%9}, {%0,%1,%2,%3};\n"
        : "+f"(d[0]), "+f"(d[1]), "+f"(d[2]), "+f"(d[3])
        : "r"(a[0]), "r"(a[1]), "r"(a[2]), "r"(a[3]), "r"(b[0]), "r"(b[1]));
}

__device__ __forceinline__ unsigned sptr(const void* p) {
    return (unsigned)__cvta_generic_to_shared(p);
}
#define CPA(dst, src) \
    asm volatile("cp.async.cg.shared.global [%0], [%1], 16;\n" :: "r"(dst), "l"(src))
#define CPC() asm volatile("cp.async.commit_group;\n")
#define CPW1() asm volatile("cp.async.wait_group 1;\n" ::: "memory")
#define CPW2() asm volatile("cp.async.wait_group 2;\n" ::: "memory")

#define PBK 16     // K-chunk per smem stage
#define LDM 20     // m-major A-tile row stride (16 + 4 pad), words
#define LDN 132    // k-major B-tile row stride (128 + 4 pad), words
#define LDV 68     // k-major V-tile row stride (64 + 4), words

struct GemmArgs {
    const float* A;
    const float* W[3];
    const float* bias[3];
    float* C[3];
};

// ======================================================================
// GEMM: C[z][M,N] = A[M,K] @ W[z][K,N] + bias[z][N]
// CTA 128x128x16, 4 warps (64x64 each), cp.async 3-stage
// ======================================================================
#define G_SA 2560   // 128*20 words per stage
#define G_SB 2112   // 16*132 words per stage

__global__ __launch_bounds__(128) void gemm3_tc(GemmArgs ga, int M, int N, int K)
{
    extern __shared__ float smem[];
    float* sAb = smem;              // 3 * G_SA
    float* sBb = smem + 3 * G_SA;   // 3 * G_SB

    int tid = threadIdx.x, lane = tid & 31, wid = tid >> 5;
    int grp = lane >> 2, tig = lane & 3;
    int m0 = blockIdx.y * 128, n0 = blockIdx.x * 128;
    int z = blockIdx.z;
    const float* A = ga.A;
    const float* B = ga.W[z];
    const float* bias = ga.bias[z];
    float* C = ga.C[z];

    int wm = (wid >> 1) * 64, wn = (wid & 1) * 64;
    int ar = tid >> 2, ac = (tid & 3) * 4;
    int br = tid >> 5, bc = (tid & 31) * 4;

    float acc[4][8][4] = {};

    auto issue = [&](int s, int k0) {
        float* pa = sAb + s * G_SA;
        float* pb = sBb + s * G_SB;
#pragma unroll
        for (int p = 0; p < 4; p++) {
            CPA(sptr(pa + (ar + p * 32) * LDM + ac),
                &A[(size_t)(m0 + ar + p * 32) * K + k0 + ac]);
            CPA(sptr(pb + (br + p * 4) * LDN + bc),
                &B[(size_t)(k0 + br + p * 4) * N + n0 + bc]);
        }
    };

    int NIT = K / PBK;
    issue(0, 0); CPC();
    issue(1, PBK); CPC();

    for (int it = 0; it < NIT; ++it) {
        CPW1();
        __syncthreads();
        int nx = it + 2;
        if (nx < NIT) issue(nx % 3, nx * PBK);
        CPC();
        const float* sa = sAb + (it % 3) * G_SA;
        const float* sb = sBb + (it % 3) * G_SB;
#pragma unroll
        for (int ks = 0; ks < 2; ks++) {
            int kk = ks * 8 + tig;
            unsigned af[4][4], bf8[8][2];
#pragma unroll
            for (int mi = 0; mi < 4; mi++) {
                int mb = wm + mi * 16 + grp;
                af[mi][0] = f2t(sa[mb * LDM + kk]);
                af[mi][1] = f2t(sa[(mb + 8) * LDM + kk]);
                af[mi][2] = f2t(sa[mb * LDM + kk + 4]);
                af[mi][3] = f2t(sa[(mb + 8) * LDM + kk + 4]);
            }
#pragma unroll
            for (int ni = 0; ni < 8; ni++) {
                int nb = wn + ni * 8 + grp;
                bf8[ni][0] = f2t(sb[kk * LDN + nb]);
                bf8[ni][1] = f2t(sb[(kk + 4) * LDN + nb]);
            }
#pragma unroll
            for (int mi = 0; mi < 4; mi++)
#pragma unroll
                for (int ni = 0; ni < 8; ni++) mma8(acc[mi][ni], af[mi], bf8[ni]);
        }
    }

#pragma unroll
    for (int mi = 0; mi < 4; mi++) {
        int row = m0 + wm + mi * 16 + grp;
#pragma unroll
        for (int ni = 0; ni < 8; ni++) {
            int col = n0 + wn + ni * 8 + 2 * tig;
            float b0 = bias[col], b1 = bias[col + 1];
            C[(size_t)row * N + col]           = acc[mi][ni][0] + b0;
            C[(size_t)row * N + col + 1]       = acc[mi][ni][1] + b1;
            C[(size_t)(row + 8) * N + col]     = acc[mi][ni][2] + b0;
            C[(size_t)(row + 8) * N + col + 1] = acc[mi][ni][3] + b1;
        }
    }
}

// ======================================================================
// Scores+exp: attn[z,q,k] = exp((Q_z@K_z^T)*0.125) (UNNORMALIZED) +
// per-row partial sums into g_rsum[z][ntile][row].
// ======================================================================
#define S_ST 2560   // 128*20 words per stage

__global__ __launch_bounds__(128) void scores_exp_tc(
    const float* __restrict__ Q, const float* __restrict__ Km,
    float* __restrict__ attn)
{
    extern __shared__ float smem[];
    float* sAb = smem;
    float* sBb = smem + 3 * S_ST;
    __shared__ float srs[128];

    int tid = threadIdx.x, lane = tid & 31, wid = tid >> 5;
    int grp = lane >> 2, tig = lane & 3;
    int q0 = blockIdx.y * 128, n0 = blockIdx.x * 128;
    int z = blockIdx.z, b = z / NHEADS, h = z % NHEADS;
    int wm = (wid >> 1) * 64, wn = (wid & 1) * 64;
    int ar = tid >> 2, ac = (tid & 3) * 4;

    srs[tid] = 0.f;

    const float* Qb = Q + (size_t)b * SEQ * DMODEL + h * HDIM;
    const float* Kb = Km + (size_t)b * SEQ * DMODEL + h * HDIM;

    float acc[4][8][4] = {};

    auto issue = [&](int s, int k0) {
        float* pa = sAb + s * S_ST;
        float* pb = sBb + s * S_ST;
#pragma unroll
        for (int p = 0; p < 4; p++) {
            CPA(sptr(pa + (ar + p * 32) * LDM + ac),
                &Qb[(size_t)(q0 + ar + p * 32) * DMODEL + k0 + ac]);
            CPA(sptr(pb + (ar + p * 32) * LDM + ac),
                &Kb[(size_t)(n0 + ar + p * 32) * DMODEL + k0 + ac]);
        }
    };

    const int NIT = HDIM / PBK;  // 4
    issue(0, 0); CPC();
    issue(1, PBK); CPC();

    for (int it = 0; it < NIT; ++it) {
        CPW1();
        __syncthreads();
        int nx = it + 2;
        if (nx < NIT) issue(nx % 3, nx * PBK);
        CPC();
        const float* sa = sAb + (it % 3) * S_ST;
        const float* sb = sBb + (it % 3) * S_ST;
#pragma unroll
        for (int ks = 0; ks < 2; ks++) {
            int kk = ks * 8 + tig;
            unsigned af[4][4], bf8[8][2];
#pragma unroll
            for (int mi = 0; mi < 4; mi++) {
                int mb = wm + mi * 16 + grp;
                af[mi][0] = f2t(sa[mb * LDM + kk]);
                af[mi][1] = f2t(sa[(mb + 8) * LDM + kk]);
                af[mi][2] = f2t(sa[mb * LDM + kk + 4]);
                af[mi][3] = f2t(sa[(mb + 8) * LDM + kk + 4]);
            }
#pragma unroll
            for (int ni = 0; ni < 8; ni++) {
                int nb = wn + ni * 8 + grp;
                bf8[ni][0] = f2t(sb[nb * LDM + kk]);
                bf8[ni][1] = f2t(sb[nb * LDM + kk + 4]);
            }
#pragma unroll
            for (int mi = 0; mi < 4; mi++)
#pragma unroll
                for (int ni = 0; ni < 8; ni++) mma8(acc[mi][ni], af[mi], bf8[ni]);
        }
    }

    // Epilogue: e = exp(scale*s); store; reduce row partials
    float* S = attn + (size_t)z * APH;
    const float scale = 0.125f;  // 1/sqrt(64)
#pragma unroll
    for (int mi = 0; mi < 4; mi++) {
        int row = q0 + wm + mi * 16 + grp;
        float r0 = 0.f, r1 = 0.f;
#pragma unroll
        for (int ni = 0; ni < 8; ni++) {
            int col = n0 + wn + ni * 8 + 2 * tig;
            float e0 = __expf(acc[mi][ni][0] * scale);
            float e1 = __expf(acc[mi][ni][1] * scale);
            float e2 = __expf(acc[mi][ni][2] * scale);
            float e3 = __expf(acc[mi][ni][3] * scale);
            S[(size_t)row * SEQ + col]           = e0;
            S[(size_t)row * SEQ + col + 1]       = e1;
            S[(size_t)(row + 8) * SEQ + col]     = e2;
            S[(size_t)(row + 8) * SEQ + col + 1] = e3;
            r0 += e0 + e1;
            r1 += e2 + e3;
        }
        r0 += __shfl_xor_sync(~0u, r0, 1); r0 += __shfl_xor_sync(~0u, r0, 2);
        r1 += __shfl_xor_sync(~0u, r1, 1); r1 += __shfl_xor_sync(~0u, r1, 2);
        if (tig == 0) {
            atomicAdd(&srs[wm + mi * 16 + grp], r0);
            atomicAdd(&srs[wm + mi * 16 + grp + 8], r1);
        }
    }
    __syncthreads();
    g_rsum[((size_t)z * 16 + blockIdx.x) * 2048 + q0 + tid] = srs[tid];
}

// ======================================================================
// AV + normalize: reads exp-attn, writes normalized attn back (streamed),
// ctx = (exp-attn @ V) * inv_row   (normalization in epilogue).
// CTA 256x64 full-K; 8 warps (32x64 each, M-split); cp.async 4-stage.
// Single wave: grid 256 CTAs @ 2/SM. No atomics.
// ======================================================================
#define V_SA 5120   // 256*20 words per stage
#define V_SB 1088   // 16*68 words per stage

__global__ __launch_bounds__(256, 2) void av_tc(
    float* __restrict__ attn, const float* __restrict__ V,
    float* __restrict__ ctx)
{
    extern __shared__ float smem[];
    float* sAb = smem;                         // 4 * V_SA
    float* sBb = smem + 4 * V_SA;              // 4 * V_SB
    float* sinv = smem + 4 * V_SA + 4 * V_SB;  // 256 row inverses

    int tid = threadIdx.x, lane = tid & 31, wid = tid >> 5;
    int grp = lane >> 2, tig = lane & 3;
    int m0 = blockIdx.x * 256;
    int z = blockIdx.y, b = z / NHEADS, h = z % NHEADS;
    int wm = wid * 32;                       // 8 warps split M, all share N=64
    int ar = tid >> 2, ac = (tid & 3) * 4;   // A: rows ar+p*64 (p<4), k-cols ac
    int rv = tid >> 4, cv = (tid & 15) * 4;  // V: k-row rv, n-cols cv

    float* Ab = attn + (size_t)z * APH;
    const float* Vb = V + (size_t)b * SEQ * DMODEL + h * HDIM;

    // Row inverse sums from the 16 scores partials
    {
        float s0 = 0.f;
        const float* rp = &g_rsum[(size_t)z * 16 * 2048 + m0];
#pragma unroll
        for (int t = 0; t < 16; t++) s0 += rp[t * 2048 + tid];
        sinv[tid] = 1.f / s0;
    }

    float acc[2][8][4] = {};

    auto issue = [&](int s, int k0) {
        float* pa = sAb + s * V_SA;
        float* pb = sBb + s * V_SB;
#pragma unroll
        for (int p = 0; p < 4; p++)
            CPA(sptr(pa + (ar + p * 64) * LDM + ac),
                &Ab[(size_t)(m0 + ar + p * 64) * SEQ + k0 + ac]);
        CPA(sptr(pb + rv * LDV + cv),
            &Vb[(size_t)(k0 + rv) * DMODEL + cv]);
    };

    const int NIT = SEQ / PBK;  // 128
    issue(0, 0); CPC();
    issue(1, PBK); CPC();
    issue(2, 2 * PBK); CPC();
    __syncthreads();   // sinv visible to all threads

    // Per-thread row inverses for the write-back rows (loop-invariant)
    float winv[4];
#pragma unroll
    for (int p = 0; p < 4; p++) winv[p] = sinv[ar + p * 64];

    for (int it = 0; it < NIT; ++it) {
        CPW2();
        __syncthreads();
        int nx = it + 3;
        if (nx < NIT) issue(nx & 3, nx * PBK);
        CPC();
        const float* sa = sAb + (it & 3) * V_SA;
        const float* sb = sBb + (it & 3) * V_SB;
#pragma unroll
        for (int ks = 0; ks < 2; ks++) {
            int kk = ks * 8 + tig;
            unsigned af[2][4], bf8[8][2];
#pragma unroll
            for (int mi = 0; mi < 2; mi++) {
                int mb = wm + mi * 16 + grp;
                af[mi][0] = f2t(sa[mb * LDM + kk]);
                af[mi][1] = f2t(sa[(mb + 8) * LDM + kk]);
                af[mi][2] = f2t(sa[mb * LDM + kk + 4]);
                af[mi][3] = f2t(sa[(mb + 8) * LDM + kk + 4]);
            }
#pragma unroll
            for (int ni = 0; ni < 8; ni++) {
                int nb = ni * 8 + grp;
                bf8[ni][0] = f2t(sb[kk * LDV + nb]);
                bf8[ni][1] = f2t(sb[(kk + 4) * LDV + nb]);
            }
#pragma unroll
            for (int mi = 0; mi < 2; mi++)
#pragma unroll
                for (int ni = 0; ni < 8; ni++) mma8(acc[mi][ni], af[mi], bf8[ni]);
        }
        // Write back normalized attn for this tile (each thread stores what
        // it loaded: rows ar+p*64, cols it*PBK + ac .. +3)
        {
            int kg = it * PBK + ac;
#pragma unroll
            for (int p = 0; p < 4; p++) {
                const float* src = sa + (ar + p * 64) * LDM + ac;
                float4 t;
                t.x = src[0] * winv[p];
                t.y = src[1] * winv[p];
                t.z = src[2] * winv[p];
                t.w = src[3] * winv[p];
                *(float4*)&Ab[(size_t)(m0 + ar + p * 64) * SEQ + kg] = t;
            }
        }
    }

    // Epilogue: normalized ctx (plain stores — full K in this CTA)
    float* Cb = ctx + (size_t)b * SEQ * DMODEL + h * HDIM;
#pragma unroll
    for (int mi = 0; mi < 2; mi++) {
        int mb = wm + mi * 16 + grp;
        int row = m0 + mb;
        float i0 = sinv[mb], i1 = sinv[mb + 8];
#pragma unroll
        for (int ni = 0; ni < 8; ni++) {
            int col = ni * 8 + 2 * tig;
            Cb[(size_t)row * DMODEL + col]           = acc[mi][ni][0] * i0;
            Cb[(size_t)row * DMODEL + col + 1]       = acc[mi][ni][1] * i0;
            Cb[(size_t)(row + 8) * DMODEL + col]     = acc[mi][ni][2] * i1;
            Cb[(size_t)(row + 8) * DMODEL + col + 1] = acc[mi][ni][3] * i1;
        }
    }
}

extern "C" void kernel_launch(void* const* d_in, const int* in_sizes, int n_in,
                              void* d_out, int out_size) {
    const float* x   = (const float*)d_in[0];
    const float* w_q = (const float*)d_in[1];
    const float* b_q = (const float*)d_in[2];
    const float* w_k = (const float*)d_in[3];
    const float* b_k = (const float*)d_in[4];
    const float* w_v = (const float*)d_in[5];
    const float* b_v = (const float*)d_in[6];
    const float* w_o = (const float*)d_in[7];
    const float* b_o = (const float*)d_in[8];

    float* out  = (float*)d_out;
    float* attn = out + OUT_ELEMS;

    float *q, *k, *v, *ctx;
    cudaGetSymbolAddress((void**)&q,   g_q);
    cudaGetSymbolAddress((void**)&k,   g_k);
    cudaGetSymbolAddress((void**)&v,   g_v);
    cudaGetSymbolAddress((void**)&ctx, g_ctx);

    const int gemmSmem   = (3 * G_SA + 3 * G_SB) * 4;          // 56064 B
    const int scoresSmem = (6 * S_ST) * 4;                     // 61440 B
    const int avSmem     = (4 * V_SA + 4 * V_SB + 256) * 4;    // 100352 B
    cudaFuncSetAttribute(gemm3_tc,      cudaFuncAttributeMaxDynamicSharedMemorySize, gemmSmem);
    cudaFuncSetAttribute(scores_exp_tc, cudaFuncAttributeMaxDynamicSharedMemorySize, scoresSmem);
    cudaFuncSetAttribute(av_tc,         cudaFuncAttributeMaxDynamicSharedMemorySize, avSmem);

    // Fused QKV projections
    GemmArgs qkv;
    qkv.A = x;
    qkv.W[0] = w_q; qkv.W[1] = w_k; qkv.W[2] = w_v;
    qkv.bias[0] = b_q; qkv.bias[1] = b_k; qkv.bias[2] = b_v;
    qkv.C[0] = q; qkv.C[1] = k; qkv.C[2] = v;
    dim3 g1(DMODEL / 128, MTOT / 128, 3);
    gemm3_tc<<<g1, 128, gemmSmem>>>(qkv, MTOT, DMODEL, DMODEL);

    // Scores + exp + row-sum partials
    dim3 g2(SEQ / 128, SEQ / 128, BATCH * NHEADS);
    scores_exp_tc<<<g2, 128, scoresSmem>>>(q, k, attn);

    // ctx = softmax @ V (normalization fused); normalized attn written back
    dim3 g3(SEQ / 256, BATCH * NHEADS);
    av_tc<<<g3, 256, avSmem>>>(attn, v, ctx);

    // out = ctx @ w_o + b_o (single launch, bias epilogue)
    GemmArgs op;
    op.A = ctx;
    op.W[0] = w_o; op.W[1] = w_o; op.W[2] = w_o;
    op.bias[0] = b_o; op.bias[1] = b_o; op.bias[2] = b_o;
    op.C[0] = out; op.C[1] = out; op.C[2] = out;
    dim3 g4(DMODEL / 128, MTOT / 128, 1);
    gemm3_tc<<<g4, 128, gemmSmem>>>(op, MTOT, DMODEL, DMODEL);
}